// round 1
// baseline (speedup 1.0000x reference)
#include <cuda_runtime.h>
#include <cstdint>

#define FULLM 0xFFFFFFFFu
#define BIGF  3.402823466e+38f

__device__ float g_feat[256*1024*16]; // stage-1 per-point features (B,N,16)
__device__ float g_fs[256*512*8];     // squeezed features on xyz1 (B,512,8)
__device__ float g_f2[256*128*128];   // stage-2 pointconv out (B,128,128)

__device__ __forceinline__ float lrelu(float x){ return x > 0.f ? x : 0.2f*x; }

// ---------------------------------------------------------------------------
// Kernel A: f = lrelu(LN(lrelu(LN(xyz@W0+b0))@W1+b1))  per point
// ---------------------------------------------------------------------------
__global__ void __launch_bounds__(256) kA(
    const float* __restrict__ pc,
    const float* __restrict__ W0, const float* __restrict__ b0,
    const float* __restrict__ g0, const float* __restrict__ be0,
    const float* __restrict__ W1, const float* __restrict__ b1,
    const float* __restrict__ g1, const float* __restrict__ be1)
{
    int i = blockIdx.x*256 + threadIdx.x;     // i in [0, 256*1024)
    int b = i >> 10, n = i & 1023;
    const float* p = pc + (size_t)b*3072;
    float x = p[n], y = p[1024+n], z = p[2048+n];

    float t[16];
    #pragma unroll
    for (int c=0;c<16;c++)
        t[c] = fmaf(x, __ldg(&W0[c]), fmaf(y, __ldg(&W0[16+c]), fmaf(z, __ldg(&W0[32+c]), __ldg(&b0[c]))));
    {
        float m=0.f;
        #pragma unroll
        for (int c=0;c<16;c++) m += t[c];
        m *= (1.f/16.f);
        float v=0.f;
        #pragma unroll
        for (int c=0;c<16;c++){ float d=t[c]-m; v = fmaf(d,d,v); }
        v *= (1.f/16.f);
        float inv = rsqrtf(v + 1e-5f);
        #pragma unroll
        for (int c=0;c<16;c++)
            t[c] = lrelu(fmaf((t[c]-m)*inv, __ldg(&g0[c]), __ldg(&be0[c])));
    }
    float u[16];
    #pragma unroll
    for (int o=0;o<16;o++){
        float a = __ldg(&b1[o]);
        #pragma unroll
        for (int c=0;c<16;c++) a = fmaf(t[c], __ldg(&W1[c*16+o]), a);
        u[o] = a;
    }
    {
        float m=0.f;
        #pragma unroll
        for (int c=0;c<16;c++) m += u[c];
        m *= (1.f/16.f);
        float v=0.f;
        #pragma unroll
        for (int c=0;c<16;c++){ float d=u[c]-m; v = fmaf(d,d,v); }
        v *= (1.f/16.f);
        float inv = rsqrtf(v + 1e-5f);
        #pragma unroll
        for (int c=0;c<16;c++)
            u[c] = lrelu(fmaf((u[c]-m)*inv, __ldg(&g1[c]), __ldg(&be1[c])));
    }
    float4* o4 = reinterpret_cast<float4*>(g_feat + (size_t)i*16);
    o4[0] = make_float4(u[0],u[1],u[2],u[3]);
    o4[1] = make_float4(u[4],u[5],u[6],u[7]);
    o4[2] = make_float4(u[8],u[9],u[10],u[11]);
    o4[3] = make_float4(u[12],u[13],u[14],u[15]);
}

// ---------------------------------------------------------------------------
// Kernel B: pointconv1 (KNN K=16 of 512 queries over 1024 pts) + fused squeeze
// One block = (batch b, half of queries). One warp = one query at a time.
// ---------------------------------------------------------------------------
__global__ void __launch_bounds__(256) kB(
    const float* __restrict__ pc,
    const float* __restrict__ Wp, const float* __restrict__ bp,
    const float* __restrict__ Ws, const float* __restrict__ bsv)
{
    __shared__ float sx[1024*3];
    __shared__ float sn[1024];
    __shared__ float sg[8][16][20];

    int b    = blockIdx.y;
    int base = blockIdx.x * 256;
    int tid  = threadIdx.x;
    int lane = tid & 31;
    int w    = tid >> 5;

    const float* p = pc + (size_t)b*3072;
    for (int t = tid; t < 3072; t += 256){
        int d = t >> 10, n = t & 1023;
        sx[n*3+d] = p[t];
    }
    __syncthreads();
    for (int n = tid; n < 1024; n += 256){
        float X=sx[3*n], Y=sx[3*n+1], Z=sx[3*n+2];
        sn[n] = fmaf(X,X, fmaf(Y,Y, Z*Z));
    }
    __syncthreads();

    float wr[19];
    #pragma unroll
    for (int c=0;c<19;c++) wr[c] = __ldg(&Wp[c*32 + lane]);
    float bias = __ldg(&bp[lane]);
    float wf[8], bsr[8];
    #pragma unroll
    for (int j=0;j<8;j++){ wf[j] = __ldg(&Ws[lane*8 + j]); bsr[j] = __ldg(&bsv[j]); }

    for (int m = base + w; m < base + 256; m += 8){
        int qi = 2*m;                                   // xyz1[m] == xyz0[2m]
        float qx = sx[3*qi], qy = sx[3*qi+1], qz = sx[3*qi+2];
        float qn2 = sn[qi];

        // --- per-lane sorted top-16 over its 32 candidates -----------------
        float dl[16]; int il[16];
        #pragma unroll
        for (int pq=0; pq<16; pq++){ dl[pq]=BIGF; il[pq]=0x7FFFFFFF; }

        #pragma unroll 1
        for (int t=0; t<32; t++){
            int j = lane + t*32;                        // strictly increasing per lane
            float dot = fmaf(qx, sx[3*j], fmaf(qy, sx[3*j+1], qz*sx[3*j+2]));
            float d = qn2 + sn[j] - 2.f*dot;
            if (d < dl[15]){
                dl[15]=d; il[15]=j;
                #pragma unroll
                for (int pq=15; pq>0; --pq){
                    if (dl[pq] < dl[pq-1]){             // strict < => stable (smaller idx first)
                        float td=dl[pq]; dl[pq]=dl[pq-1]; dl[pq-1]=td;
                        int   ti=il[pq]; il[pq]=il[pq-1]; il[pq-1]=ti;
                    }
                }
            }
        }

        // --- 16 rounds warp argmin over heads (tie-break by index) ---------
        int kidx = 0;
        #pragma unroll 1
        for (int r=0;r<16;r++){
            float md = dl[0]; int mi = il[0];
            #pragma unroll
            for (int off=16; off>0; off>>=1){
                float od = __shfl_down_sync(FULLM, md, off);
                int   oi = __shfl_down_sync(FULLM, mi, off);
                if (od < md || (od == md && oi < mi)){ md=od; mi=oi; }
            }
            mi = __shfl_sync(FULLM, mi, 0);
            if (lane == r) kidx = mi;
            if (il[0] == mi){                            // winner pops its head
                #pragma unroll
                for (int pq=0; pq<15; pq++){ dl[pq]=dl[pq+1]; il[pq]=il[pq+1]; }
                dl[15]=BIGF; il[15]=0x7FFFFFFF;
            }
        }

        // --- gather neighbors into per-warp smem g[16][19] ------------------
        __syncwarp();
        if (lane < 16){
            int j = kidx;
            float* gr = &sg[w][lane][0];
            gr[0]=sx[3*j]-qx; gr[1]=sx[3*j+1]-qy; gr[2]=sx[3*j+2]-qz;
            const float4* fr = reinterpret_cast<const float4*>(g_feat + ((size_t)b*1024 + j)*16);
            float4 f0=fr[0], f1=fr[1], f2v=fr[2], f3=fr[3];
            gr[3]=f0.x;  gr[4]=f0.y;  gr[5]=f0.z;  gr[6]=f0.w;
            gr[7]=f1.x;  gr[8]=f1.y;  gr[9]=f1.z;  gr[10]=f1.w;
            gr[11]=f2v.x; gr[12]=f2v.y; gr[13]=f2v.z; gr[14]=f2v.w;
            gr[15]=f3.x; gr[16]=f3.y; gr[17]=f3.z; gr[18]=f3.w;
        }
        __syncwarp();

        // --- GEMM (lane = output channel of 32) + lrelu + maxpool ----------
        float mx = -BIGF;
        #pragma unroll 4
        for (int k=0;k<16;k++){
            float a = bias;
            const float* gr = &sg[w][k][0];
            #pragma unroll
            for (int c=0;c<19;c++) a = fmaf(gr[c], wr[c], a);
            mx = fmaxf(mx, lrelu(a));
        }

        // --- fused squeeze: fs = lrelu(mx_vec @ Ws + bs) --------------------
        float pj[8];
        #pragma unroll
        for (int j=0;j<8;j++) pj[j] = mx * wf[j];
        #pragma unroll
        for (int off=16; off>0; off>>=1){
            #pragma unroll
            for (int j=0;j<8;j++) pj[j] += __shfl_down_sync(FULLM, pj[j], off);
        }
        if (lane == 0){
            float* o = g_fs + ((size_t)b*512 + m)*8;
            #pragma unroll
            for (int j=0;j<8;j++) o[j] = lrelu(pj[j] + bsr[j]);
        }
    }
}

// ---------------------------------------------------------------------------
// Kernel C: pointconv2 (128 queries, 512 candidates, 11ch -> 128ch)
// ---------------------------------------------------------------------------
__global__ void __launch_bounds__(256) kC(
    const float* __restrict__ pc,
    const float* __restrict__ Wc, const float* __restrict__ bc)
{
    __shared__ float sx[512*3];
    __shared__ float sn[512];
    __shared__ float sf[512*8];
    __shared__ float sg[8][16][12];

    int b    = blockIdx.x;
    int tid  = threadIdx.x;
    int lane = tid & 31;
    int w    = tid >> 5;

    const float* p = pc + (size_t)b*3072;
    for (int t = tid; t < 1536; t += 256){
        int d = t / 512, m = t % 512;
        sx[m*3+d] = p[d*1024 + 2*m];                    // xyz1[m] = xyz0[2m]
    }
    {
        const float4* src = reinterpret_cast<const float4*>(g_fs + (size_t)b*4096);
        float4* dst = reinterpret_cast<float4*>(sf);
        for (int t = tid; t < 1024; t += 256) dst[t] = src[t];
    }
    __syncthreads();
    for (int n = tid; n < 512; n += 256){
        float X=sx[3*n], Y=sx[3*n+1], Z=sx[3*n+2];
        sn[n] = fmaf(X,X, fmaf(Y,Y, Z*Z));
    }
    __syncthreads();

    float wc0[11], wc1[11], wc2[11], wc3[11];
    #pragma unroll
    for (int c=0;c<11;c++){
        wc0[c] = __ldg(&Wc[c*128 + lane]);
        wc1[c] = __ldg(&Wc[c*128 + lane + 32]);
        wc2[c] = __ldg(&Wc[c*128 + lane + 64]);
        wc3[c] = __ldg(&Wc[c*128 + lane + 96]);
    }
    float bc0 = __ldg(&bc[lane]),    bc1 = __ldg(&bc[lane+32]);
    float bc2 = __ldg(&bc[lane+64]), bc3 = __ldg(&bc[lane+96]);

    for (int m2 = w; m2 < 128; m2 += 8){
        int qi = 4*m2;                                  // xyz2[m2] == xyz1[4*m2]
        float qx = sx[3*qi], qy = sx[3*qi+1], qz = sx[3*qi+2];
        float qn2 = sn[qi];

        float dl[16]; int il[16];
        #pragma unroll
        for (int pq=0; pq<16; pq++){ dl[pq]=BIGF; il[pq]=0x7FFFFFFF; }

        #pragma unroll 1
        for (int t=0; t<16; t++){
            int j = lane + t*32;
            float dot = fmaf(qx, sx[3*j], fmaf(qy, sx[3*j+1], qz*sx[3*j+2]));
            float d = qn2 + sn[j] - 2.f*dot;
            if (d < dl[15]){
                dl[15]=d; il[15]=j;
                #pragma unroll
                for (int pq=15; pq>0; --pq){
                    if (dl[pq] < dl[pq-1]){
                        float td=dl[pq]; dl[pq]=dl[pq-1]; dl[pq-1]=td;
                        int   ti=il[pq]; il[pq]=il[pq-1]; il[pq-1]=ti;
                    }
                }
            }
        }

        int kidx = 0;
        #pragma unroll 1
        for (int r=0;r<16;r++){
            float md = dl[0]; int mi = il[0];
            #pragma unroll
            for (int off=16; off>0; off>>=1){
                float od = __shfl_down_sync(FULLM, md, off);
                int   oi = __shfl_down_sync(FULLM, mi, off);
                if (od < md || (od == md && oi < mi)){ md=od; mi=oi; }
            }
            mi = __shfl_sync(FULLM, mi, 0);
            if (lane == r) kidx = mi;
            if (il[0] == mi){
                #pragma unroll
                for (int pq=0; pq<15; pq++){ dl[pq]=dl[pq+1]; il[pq]=il[pq+1]; }
                dl[15]=BIGF; il[15]=0x7FFFFFFF;
            }
        }

        __syncwarp();
        if (lane < 16){
            int j = kidx;
            float* gr = &sg[w][lane][0];
            gr[0]=sx[3*j]-qx; gr[1]=sx[3*j+1]-qy; gr[2]=sx[3*j+2]-qz;
            const float4* fr = reinterpret_cast<const float4*>(sf + j*8);
            float4 f0=fr[0], f1=fr[1];
            gr[3]=f0.x; gr[4]=f0.y; gr[5]=f0.z; gr[6]=f0.w;
            gr[7]=f1.x; gr[8]=f1.y; gr[9]=f1.z; gr[10]=f1.w;
        }
        __syncwarp();

        float mx0=-BIGF, mx1=-BIGF, mx2=-BIGF, mx3=-BIGF;
        #pragma unroll 4
        for (int k=0;k<16;k++){
            float a0=bc0, a1=bc1, a2=bc2, a3=bc3;
            const float* gr = &sg[w][k][0];
            #pragma unroll
            for (int c=0;c<11;c++){
                float gv = gr[c];
                a0 = fmaf(gv, wc0[c], a0);
                a1 = fmaf(gv, wc1[c], a1);
                a2 = fmaf(gv, wc2[c], a2);
                a3 = fmaf(gv, wc3[c], a3);
            }
            mx0 = fmaxf(mx0, lrelu(a0));
            mx1 = fmaxf(mx1, lrelu(a1));
            mx2 = fmaxf(mx2, lrelu(a2));
            mx3 = fmaxf(mx3, lrelu(a3));
        }
        float* o = g_f2 + ((size_t)b*128 + m2)*128;
        o[lane]    = mx0;
        o[lane+32] = mx1;
        o[lane+64] = mx2;
        o[lane+96] = mx3;
    }
}

// ---------------------------------------------------------------------------
// Kernel D: out[b] = mean_m(f2[b]) @ We + be   (mean commutes with linear map)
// ---------------------------------------------------------------------------
__global__ void __launch_bounds__(256) kD(
    const float* __restrict__ We, const float* __restrict__ be,
    float* __restrict__ out)
{
    __shared__ float sbar[128];
    int b = blockIdx.x, tid = threadIdx.x;
    const float* f2 = g_f2 + (size_t)b*128*128;
    if (tid < 128){
        float s = 0.f;
        #pragma unroll 8
        for (int m=0;m<128;m++) s += f2[m*128 + tid];
        sbar[tid] = s * (1.f/128.f);
    }
    __syncthreads();
    float acc = __ldg(&be[tid]);
    #pragma unroll 8
    for (int c=0;c<128;c++) acc = fmaf(sbar[c], __ldg(&We[c*256 + tid]), acc);
    out[(size_t)b*256 + tid] = acc;
}

// ---------------------------------------------------------------------------
extern "C" void kernel_launch(void* const* d_in, const int* in_sizes, int n_in,
                              void* d_out, int out_size)
{
    (void)in_sizes; (void)n_in; (void)out_size;
    const float* pc  = (const float*)d_in[0];
    const float* W0  = (const float*)d_in[1];
    const float* b0  = (const float*)d_in[2];
    const float* g0  = (const float*)d_in[3];
    const float* be0 = (const float*)d_in[4];
    const float* W1  = (const float*)d_in[5];
    const float* b1  = (const float*)d_in[6];
    const float* g1  = (const float*)d_in[7];
    const float* be1 = (const float*)d_in[8];
    const float* Wp  = (const float*)d_in[9];
    const float* bp  = (const float*)d_in[10];
    const float* Ws  = (const float*)d_in[11];
    const float* bsv = (const float*)d_in[12];
    const float* Wc  = (const float*)d_in[13];
    const float* bc  = (const float*)d_in[14];
    const float* We  = (const float*)d_in[15];
    const float* be  = (const float*)d_in[16];
    float* out = (float*)d_out;

    kA<<<1024, 256>>>(pc, W0, b0, g0, be0, W1, b1, g1, be1);
    dim3 gB(2, 256);
    kB<<<gB, 256>>>(pc, Wp, bp, Ws, bsv);
    kC<<<256, 256>>>(pc, Wc, bc);
    kD<<<256, 256>>>(We, be, out);
}

// round 2
// speedup vs baseline: 2.7570x; 2.7570x over previous
#include <cuda_runtime.h>
#include <cstdint>

#define FULLM 0xFFFFFFFFu
#define BIGF  3.402823466e+38f

__device__ float g_feat[256*1024*16]; // stage-1 per-point features (B,N,16)
__device__ float g_fs[256*512*8];     // squeezed features on xyz1 (B,512,8)
__device__ float g_f2[256*128*128];   // stage-2 pointconv out (B,128,128)

__device__ __forceinline__ float lrelu(float x){ return x > 0.f ? x : 0.2f*x; }

__device__ __forceinline__ float distf(const float* __restrict__ sx,
                                       const float* __restrict__ sn, int j,
                                       float qx, float qy, float qz, float qn2){
    float dot = fmaf(qx, sx[3*j], fmaf(qy, sx[3*j+1], qz*sx[3*j+2]));
    return qn2 + sn[j] - 2.f*dot;
}

// Bitonic sort of 32 (d,i) pairs across a warp, ascending lex (d, then i).
__device__ __forceinline__ void bsort32(float& d, int& i, int lane){
    #pragma unroll
    for (int k = 2; k <= 32; k <<= 1){
        #pragma unroll
        for (int j = k >> 1; j > 0; j >>= 1){
            float od = __shfl_xor_sync(FULLM, d, j);
            int   oi = __shfl_xor_sync(FULLM, i, j);
            bool lower = (lane & j) == 0;
            bool asc   = (lane & k) == 0;
            bool osm   = (od < d) || (od == d && oi < i);
            bool take  = (lower == asc) ? osm : !osm;
            if (take){ d = od; i = oi; }
        }
    }
}

// Exact top-16 of NT*32 candidates (xyz in sx, norms in sn). Returns the
// lane-th nearest index on lanes 0..15 (ascending (d,idx) order).
// scand/sidxs: per-warp 32-slot smem scratch.
template<int NT>
__device__ __forceinline__ int knn16_select(
    const float* __restrict__ sx, const float* __restrict__ sn,
    float qx, float qy, float qz, float qn2, int lane,
    float* scand, int* sidxs)
{
    // --- phase 1: per-lane argmin (two independent chains for ILP) ---------
    float bdA = BIGF, bdB = BIGF; int biA = 0x7FFFFFFF, biB = 0x7FFFFFFF;
    #pragma unroll
    for (int t = 0; t < NT/2; t++){
        int j = lane + t*32;
        float d = distf(sx, sn, j, qx, qy, qz, qn2);
        if (d < bdA){ bdA = d; biA = j; }
    }
    #pragma unroll
    for (int t = NT/2; t < NT; t++){
        int j = lane + t*32;
        float d = distf(sx, sn, j, qx, qy, qz, qn2);
        if (d < bdB){ bdB = d; biB = j; }
    }
    float bd = bdA; int bi = biA;
    if (bdB < bdA){ bd = bdB; bi = biB; }   // chain B indices > chain A

    // --- phase 2: threshold = 16th-smallest lane minimum (valid bound) -----
    bsort32(bd, bi, lane);
    float thr = __shfl_sync(FULLM, bd, 15);

    // --- phase 3: ballot-compact all d <= thr into 32-slot buffer ----------
    scand[lane] = BIGF; sidxs[lane] = 0x7FFFFFFF;
    __syncwarp();
    unsigned lt = (1u << lane) - 1u;
    int cnt = 0;
    #pragma unroll
    for (int t = 0; t < NT; t++){
        int j = lane + t*32;
        float d = distf(sx, sn, j, qx, qy, qz, qn2);
        bool p = (d <= thr);
        unsigned mask = __ballot_sync(FULLM, p);
        if (p){
            int pos = cnt + __popc(mask & lt);
            if (pos < 32){ scand[pos] = d; sidxs[pos] = j; }
        }
        cnt += __popc(mask);
    }
    __syncwarp();

    int kidx;
    if (cnt <= 32){
        // --- phase 4: sort the <=32 qualifiers; lanes 0..15 = top-16 -------
        float d2 = scand[lane]; int i2 = sidxs[lane];
        bsort32(d2, i2, lane);
        kidx = i2;
    } else {
        // --- rare fallback: progressive argmin with lex exclusion ----------
        float lastD = -BIGF; int lastI = -1; kidx = 0x7FFFFFFF;
        for (int r = 0; r < 16; r++){
            float cbd = BIGF; int cbi = 0x7FFFFFFF;
            #pragma unroll
            for (int t = 0; t < NT; t++){
                int j = lane + t*32;
                float d = distf(sx, sn, j, qx, qy, qz, qn2);
                bool gt = (d > lastD) || (d == lastD && j > lastI);
                if (gt && ((d < cbd) || (d == cbd && j < cbi))){ cbd = d; cbi = j; }
            }
            #pragma unroll
            for (int off = 16; off > 0; off >>= 1){
                float od = __shfl_down_sync(FULLM, cbd, off);
                int   oi = __shfl_down_sync(FULLM, cbi, off);
                if (od < cbd || (od == cbd && oi < cbi)){ cbd = od; cbi = oi; }
            }
            lastD = __shfl_sync(FULLM, cbd, 0);
            lastI = __shfl_sync(FULLM, cbi, 0);
            if (lane == r) kidx = lastI;
        }
    }
    return kidx;
}

// ---------------------------------------------------------------------------
// Kernel A: f = lrelu(LN(lrelu(LN(xyz@W0+b0))@W1+b1))  per point
// ---------------------------------------------------------------------------
__global__ void __launch_bounds__(256) kA(
    const float* __restrict__ pc,
    const float* __restrict__ W0, const float* __restrict__ b0,
    const float* __restrict__ g0, const float* __restrict__ be0,
    const float* __restrict__ W1, const float* __restrict__ b1,
    const float* __restrict__ g1, const float* __restrict__ be1)
{
    int i = blockIdx.x*256 + threadIdx.x;
    int b = i >> 10, n = i & 1023;
    const float* p = pc + (size_t)b*3072;
    float x = p[n], y = p[1024+n], z = p[2048+n];

    float t[16];
    #pragma unroll
    for (int c=0;c<16;c++)
        t[c] = fmaf(x, __ldg(&W0[c]), fmaf(y, __ldg(&W0[16+c]), fmaf(z, __ldg(&W0[32+c]), __ldg(&b0[c]))));
    {
        float m=0.f;
        #pragma unroll
        for (int c=0;c<16;c++) m += t[c];
        m *= (1.f/16.f);
        float v=0.f;
        #pragma unroll
        for (int c=0;c<16;c++){ float d=t[c]-m; v = fmaf(d,d,v); }
        v *= (1.f/16.f);
        float inv = rsqrtf(v + 1e-5f);
        #pragma unroll
        for (int c=0;c<16;c++)
            t[c] = lrelu(fmaf((t[c]-m)*inv, __ldg(&g0[c]), __ldg(&be0[c])));
    }
    float u[16];
    #pragma unroll
    for (int o=0;o<16;o++){
        float a = __ldg(&b1[o]);
        #pragma unroll
        for (int c=0;c<16;c++) a = fmaf(t[c], __ldg(&W1[c*16+o]), a);
        u[o] = a;
    }
    {
        float m=0.f;
        #pragma unroll
        for (int c=0;c<16;c++) m += u[c];
        m *= (1.f/16.f);
        float v=0.f;
        #pragma unroll
        for (int c=0;c<16;c++){ float d=u[c]-m; v = fmaf(d,d,v); }
        v *= (1.f/16.f);
        float inv = rsqrtf(v + 1e-5f);
        #pragma unroll
        for (int c=0;c<16;c++)
            u[c] = lrelu(fmaf((u[c]-m)*inv, __ldg(&g1[c]), __ldg(&be1[c])));
    }
    float4* o4 = reinterpret_cast<float4*>(g_feat + (size_t)i*16);
    o4[0] = make_float4(u[0],u[1],u[2],u[3]);
    o4[1] = make_float4(u[4],u[5],u[6],u[7]);
    o4[2] = make_float4(u[8],u[9],u[10],u[11]);
    o4[3] = make_float4(u[12],u[13],u[14],u[15]);
}

// ---------------------------------------------------------------------------
// Kernel B: pointconv1 (K=16 NN of 512 queries over 1024 pts) + fused squeeze
// grid (4, B): 128 queries per block, one warp per query.
// ---------------------------------------------------------------------------
__global__ void __launch_bounds__(256) kB(
    const float* __restrict__ pc,
    const float* __restrict__ Wp, const float* __restrict__ bp,
    const float* __restrict__ Ws, const float* __restrict__ bsv)
{
    __shared__ float sx[1024*3];
    __shared__ float sn[1024];
    __shared__ float sg[8][16][20];
    __shared__ float scand[8][32];
    __shared__ int   sidxs[8][32];

    int b    = blockIdx.y;
    int base = blockIdx.x * 128;
    int tid  = threadIdx.x;
    int lane = tid & 31;
    int w    = tid >> 5;

    const float* p = pc + (size_t)b*3072;
    for (int t = tid; t < 3072; t += 256){
        int d = t >> 10, n = t & 1023;
        sx[n*3+d] = p[t];
    }
    __syncthreads();
    for (int n = tid; n < 1024; n += 256){
        float X=sx[3*n], Y=sx[3*n+1], Z=sx[3*n+2];
        sn[n] = fmaf(X,X, fmaf(Y,Y, Z*Z));
    }
    __syncthreads();

    float wr[19];
    #pragma unroll
    for (int c=0;c<19;c++) wr[c] = __ldg(&Wp[c*32 + lane]);
    float bias = __ldg(&bp[lane]);
    float wf[8], bsr[8];
    #pragma unroll
    for (int j=0;j<8;j++){ wf[j] = __ldg(&Ws[lane*8 + j]); bsr[j] = __ldg(&bsv[j]); }

    for (int m = base + w; m < base + 128; m += 8){
        int qi = 2*m;                                   // xyz1[m] == xyz0[2m]
        float qx = sx[3*qi], qy = sx[3*qi+1], qz = sx[3*qi+2];
        float qn2 = sn[qi];

        int kidx = knn16_select<32>(sx, sn, qx, qy, qz, qn2, lane,
                                    &scand[w][0], &sidxs[w][0]);

        // --- gather neighbors into per-warp smem g[16][19] ------------------
        __syncwarp();
        if (lane < 16){
            int j = kidx;
            float* gr = &sg[w][lane][0];
            gr[0]=sx[3*j]-qx; gr[1]=sx[3*j+1]-qy; gr[2]=sx[3*j+2]-qz;
            const float4* fr = reinterpret_cast<const float4*>(g_feat + ((size_t)b*1024 + j)*16);
            float4 f0=fr[0], f1=fr[1], f2v=fr[2], f3=fr[3];
            gr[3]=f0.x;  gr[4]=f0.y;  gr[5]=f0.z;  gr[6]=f0.w;
            gr[7]=f1.x;  gr[8]=f1.y;  gr[9]=f1.z;  gr[10]=f1.w;
            gr[11]=f2v.x; gr[12]=f2v.y; gr[13]=f2v.z; gr[14]=f2v.w;
            gr[15]=f3.x; gr[16]=f3.y; gr[17]=f3.z; gr[18]=f3.w;
        }
        __syncwarp();

        // --- GEMM (lane = output channel of 32) + lrelu + maxpool ----------
        float mx = -BIGF;
        #pragma unroll 4
        for (int k=0;k<16;k++){
            const float4* gr4 = reinterpret_cast<const float4*>(&sg[w][k][0]);
            float4 v0=gr4[0], v1=gr4[1], v2=gr4[2], v3=gr4[3], v4=gr4[4];
            float a = bias;
            a = fmaf(v0.x, wr[0],  a); a = fmaf(v0.y, wr[1],  a);
            a = fmaf(v0.z, wr[2],  a); a = fmaf(v0.w, wr[3],  a);
            a = fmaf(v1.x, wr[4],  a); a = fmaf(v1.y, wr[5],  a);
            a = fmaf(v1.z, wr[6],  a); a = fmaf(v1.w, wr[7],  a);
            a = fmaf(v2.x, wr[8],  a); a = fmaf(v2.y, wr[9],  a);
            a = fmaf(v2.z, wr[10], a); a = fmaf(v2.w, wr[11], a);
            a = fmaf(v3.x, wr[12], a); a = fmaf(v3.y, wr[13], a);
            a = fmaf(v3.z, wr[14], a); a = fmaf(v3.w, wr[15], a);
            a = fmaf(v4.x, wr[16], a); a = fmaf(v4.y, wr[17], a);
            a = fmaf(v4.z, wr[18], a);
            mx = fmaxf(mx, lrelu(a));
        }

        // --- fused squeeze: fs = lrelu(mx_vec @ Ws + bs) --------------------
        float pj[8];
        #pragma unroll
        for (int j=0;j<8;j++) pj[j] = mx * wf[j];
        #pragma unroll
        for (int off=16; off>0; off>>=1){
            #pragma unroll
            for (int j=0;j<8;j++) pj[j] += __shfl_down_sync(FULLM, pj[j], off);
        }
        if (lane == 0){
            float* o = g_fs + ((size_t)b*512 + m)*8;
            #pragma unroll
            for (int j=0;j<8;j++) o[j] = lrelu(pj[j] + bsr[j]);
        }
    }
}

// ---------------------------------------------------------------------------
// Kernel C: pointconv2 (128 queries, 512 candidates, 11ch -> 128ch)
// grid (2, B): 64 queries per block, one warp per query.
// ---------------------------------------------------------------------------
__global__ void __launch_bounds__(256) kC(
    const float* __restrict__ pc,
    const float* __restrict__ Wc, const float* __restrict__ bc)
{
    __shared__ float sx[512*3];
    __shared__ float sn[512];
    __shared__ float sf[512*8];
    __shared__ float sg[8][16][12];
    __shared__ float scand[8][32];
    __shared__ int   sidxs[8][32];

    int b    = blockIdx.y;
    int base = blockIdx.x * 64;
    int tid  = threadIdx.x;
    int lane = tid & 31;
    int w    = tid >> 5;

    const float* p = pc + (size_t)b*3072;
    for (int t = tid; t < 1536; t += 256){
        int d = t / 512, m = t % 512;
        sx[m*3+d] = p[d*1024 + 2*m];                    // xyz1[m] = xyz0[2m]
    }
    {
        const float4* src = reinterpret_cast<const float4*>(g_fs + (size_t)b*4096);
        float4* dst = reinterpret_cast<float4*>(sf);
        for (int t = tid; t < 1024; t += 256) dst[t] = src[t];
    }
    __syncthreads();
    for (int n = tid; n < 512; n += 256){
        float X=sx[3*n], Y=sx[3*n+1], Z=sx[3*n+2];
        sn[n] = fmaf(X,X, fmaf(Y,Y, Z*Z));
    }
    __syncthreads();

    float wc0[11], wc1[11], wc2[11], wc3[11];
    #pragma unroll
    for (int c=0;c<11;c++){
        wc0[c] = __ldg(&Wc[c*128 + lane]);
        wc1[c] = __ldg(&Wc[c*128 + lane + 32]);
        wc2[c] = __ldg(&Wc[c*128 + lane + 64]);
        wc3[c] = __ldg(&Wc[c*128 + lane + 96]);
    }
    float bc0 = __ldg(&bc[lane]),    bc1 = __ldg(&bc[lane+32]);
    float bc2 = __ldg(&bc[lane+64]), bc3 = __ldg(&bc[lane+96]);

    for (int m2 = base + w; m2 < base + 64; m2 += 8){
        int qi = 4*m2;                                  // xyz2[m2] == xyz1[4*m2]
        float qx = sx[3*qi], qy = sx[3*qi+1], qz = sx[3*qi+2];
        float qn2 = sn[qi];

        int kidx = knn16_select<16>(sx, sn, qx, qy, qz, qn2, lane,
                                    &scand[w][0], &sidxs[w][0]);

        __syncwarp();
        if (lane < 16){
            int j = kidx;
            float* gr = &sg[w][lane][0];
            gr[0]=sx[3*j]-qx; gr[1]=sx[3*j+1]-qy; gr[2]=sx[3*j+2]-qz;
            const float4* fr = reinterpret_cast<const float4*>(sf + j*8);
            float4 f0=fr[0], f1=fr[1];
            gr[3]=f0.x; gr[4]=f0.y; gr[5]=f0.z; gr[6]=f0.w;
            gr[7]=f1.x; gr[8]=f1.y; gr[9]=f1.z; gr[10]=f1.w;
        }
        __syncwarp();

        float mx0=-BIGF, mx1=-BIGF, mx2=-BIGF, mx3=-BIGF;
        #pragma unroll 4
        for (int k=0;k<16;k++){
            const float4* gr4 = reinterpret_cast<const float4*>(&sg[w][k][0]);
            float4 v0=gr4[0], v1=gr4[1], v2=gr4[2];
            float gv[11] = {v0.x,v0.y,v0.z,v0.w, v1.x,v1.y,v1.z,v1.w, v2.x,v2.y,v2.z};
            float a0=bc0, a1=bc1, a2=bc2, a3=bc3;
            #pragma unroll
            for (int c=0;c<11;c++){
                a0 = fmaf(gv[c], wc0[c], a0);
                a1 = fmaf(gv[c], wc1[c], a1);
                a2 = fmaf(gv[c], wc2[c], a2);
                a3 = fmaf(gv[c], wc3[c], a3);
            }
            mx0 = fmaxf(mx0, lrelu(a0));
            mx1 = fmaxf(mx1, lrelu(a1));
            mx2 = fmaxf(mx2, lrelu(a2));
            mx3 = fmaxf(mx3, lrelu(a3));
        }
        float* o = g_f2 + ((size_t)b*128 + m2)*128;
        o[lane]    = mx0;
        o[lane+32] = mx1;
        o[lane+64] = mx2;
        o[lane+96] = mx3;
    }
}

// ---------------------------------------------------------------------------
// Kernel D: out[b] = mean_m(f2[b]) @ We + be   (mean commutes with linear map)
// ---------------------------------------------------------------------------
__global__ void __launch_bounds__(256) kD(
    const float* __restrict__ We, const float* __restrict__ be,
    float* __restrict__ out)
{
    __shared__ float sp[256];
    __shared__ float sbar[128];
    int b = blockIdx.x, tid = threadIdx.x;
    const float* f2 = g_f2 + (size_t)b*128*128;
    {
        int c  = tid & 127;
        int m0 = (tid >> 7) * 64;
        float s = 0.f;
        #pragma unroll 8
        for (int m=m0; m<m0+64; m++) s += f2[m*128 + c];
        sp[tid] = s;
    }
    __syncthreads();
    if (tid < 128) sbar[tid] = (sp[tid] + sp[tid+128]) * (1.f/128.f);
    __syncthreads();
    float acc = __ldg(&be[tid]);
    #pragma unroll 8
    for (int c=0;c<128;c++) acc = fmaf(sbar[c], __ldg(&We[c*256 + tid]), acc);
    out[(size_t)b*256 + tid] = acc;
}

// ---------------------------------------------------------------------------
extern "C" void kernel_launch(void* const* d_in, const int* in_sizes, int n_in,
                              void* d_out, int out_size)
{
    (void)in_sizes; (void)n_in; (void)out_size;
    const float* pc  = (const float*)d_in[0];
    const float* W0  = (const float*)d_in[1];
    const float* b0  = (const float*)d_in[2];
    const float* g0  = (const float*)d_in[3];
    const float* be0 = (const float*)d_in[4];
    const float* W1  = (const float*)d_in[5];
    const float* b1  = (const float*)d_in[6];
    const float* g1  = (const float*)d_in[7];
    const float* be1 = (const float*)d_in[8];
    const float* Wp  = (const float*)d_in[9];
    const float* bp  = (const float*)d_in[10];
    const float* Ws  = (const float*)d_in[11];
    const float* bsv = (const float*)d_in[12];
    const float* Wc  = (const float*)d_in[13];
    const float* bc  = (const float*)d_in[14];
    const float* We  = (const float*)d_in[15];
    const float* be  = (const float*)d_in[16];
    float* out = (float*)d_out;

    kA<<<1024, 256>>>(pc, W0, b0, g0, be0, W1, b1, g1, be1);
    dim3 gB(4, 256);
    kB<<<gB, 256>>>(pc, Wp, bp, Ws, bsv);
    dim3 gC(2, 256);
    kC<<<gC, 256>>>(pc, Wc, bc);
    kD<<<256, 256>>>(We, be, out);
}

// round 3
// speedup vs baseline: 3.0771x; 1.1161x over previous
#include <cuda_runtime.h>
#include <cstdint>

#define FULLM 0xFFFFFFFFu
#define BIGF  3.402823466e+38f

__device__ float g_feat[256*1024*16]; // stage-1 per-point features (B,N,16)
__device__ float g_fs[256*512*8];     // squeezed features on xyz1 (B,512,8)
__device__ float g_psum[256*2*128];   // per-block partial sums of f2 (B,2,128)

__device__ __forceinline__ float lrelu(float x){ return x > 0.f ? x : 0.2f*x; }

// Value-only bitonic sort of 32 floats across a warp (ascending).
__device__ __forceinline__ float bsort32_val(float s, int lane){
    #pragma unroll
    for (int k = 2; k <= 32; k <<= 1){
        #pragma unroll
        for (int j = k >> 1; j > 0; j >>= 1){
            float o = __shfl_xor_sync(FULLM, s, j);
            bool keepmin = ((lane & j) == 0) == ((lane & k) == 0);
            float mn = fminf(s, o), mx = fmaxf(s, o);
            s = keepmin ? mn : mx;
        }
    }
    return s;
}

// Bitonic sort of 32 (d,i) pairs across a warp, ascending lex (d, then i).
__device__ __forceinline__ void bsort32_pair(float& d, int& i, int lane){
    #pragma unroll
    for (int k = 2; k <= 32; k <<= 1){
        #pragma unroll
        for (int j = k >> 1; j > 0; j >>= 1){
            float od = __shfl_xor_sync(FULLM, d, j);
            int   oi = __shfl_xor_sync(FULLM, i, j);
            bool lower = (lane & j) == 0;
            bool asc   = (lane & k) == 0;
            bool osm   = (od < d) || (od == d && oi < i);
            bool take  = (lower == asc) ? osm : !osm;
            if (take){ d = od; i = oi; }
        }
    }
}

// Exact top-16 of NT*32 candidates. sp holds (x,y,z,|p|^2) per point.
// Returns the lane-th nearest index on lanes 0..15 (ascending (d,idx)).
template<int NT>
__device__ __forceinline__ int knn16_select(
    const float4* __restrict__ sp,
    float qx, float qy, float qz, float qn2, int lane,
    float* scand, int* sidxs)
{
    // --- phase 1: compute & register-cache all NT distances ----------------
    float d[NT];
    #pragma unroll
    for (int t = 0; t < NT; t++){
        float4 v = sp[lane + t*32];
        float dot = fmaf(qx, v.x, fmaf(qy, v.y, qz*v.z));
        d[t] = fmaf(-2.f, dot, qn2 + v.w);
    }
    // per-lane min (value only), 4 independent chains
    float m0 = d[0], m1 = d[1], m2 = d[2], m3 = d[3];
    #pragma unroll
    for (int t = 4; t < NT; t += 4){
        m0 = fminf(m0, d[t]);   m1 = fminf(m1, d[t+1]);
        m2 = fminf(m2, d[t+2]); m3 = fminf(m3, d[t+3]);
    }
    float bd = fminf(fminf(m0, m1), fminf(m2, m3));

    // --- phase 2: threshold = 16th-smallest lane minimum (valid bound) -----
    float thr = __shfl_sync(FULLM, bsort32_val(bd, lane), 15);

    // --- phase 3: ballot-compact all d <= thr into 32-slot buffer ----------
    scand[lane] = BIGF; sidxs[lane] = 0x7FFFFFFF;
    __syncwarp();
    unsigned lt = (1u << lane) - 1u;
    int cnt = 0;
    #pragma unroll
    for (int t = 0; t < NT; t++){
        bool p = (d[t] <= thr);
        unsigned mask = __ballot_sync(FULLM, p);
        if (p){
            int pos = cnt + __popc(mask & lt);
            if (pos < 32){ scand[pos] = d[t]; sidxs[pos] = lane + t*32; }
        }
        cnt += __popc(mask);
    }
    __syncwarp();

    int kidx;
    if (cnt <= 32){
        // --- phase 4: sort the <=32 qualifiers; lanes 0..15 = top-16 -------
        float d2 = scand[lane]; int i2 = sidxs[lane];
        bsort32_pair(d2, i2, lane);
        kidx = i2;
    } else {
        // --- rare fallback: progressive argmin with lex exclusion ----------
        float lastD = -BIGF; int lastI = -1; kidx = 0x7FFFFFFF;
        for (int r = 0; r < 16; r++){
            float cbd = BIGF; int cbi = 0x7FFFFFFF;
            #pragma unroll
            for (int t = 0; t < NT; t++){
                int j = lane + t*32;
                bool gt = (d[t] > lastD) || (d[t] == lastD && j > lastI);
                if (gt && ((d[t] < cbd) || (d[t] == cbd && j < cbi))){ cbd = d[t]; cbi = j; }
            }
            #pragma unroll
            for (int off = 16; off > 0; off >>= 1){
                float od = __shfl_down_sync(FULLM, cbd, off);
                int   oi = __shfl_down_sync(FULLM, cbi, off);
                if (od < cbd || (od == cbd && oi < cbi)){ cbd = od; cbi = oi; }
            }
            lastD = __shfl_sync(FULLM, cbd, 0);
            lastI = __shfl_sync(FULLM, cbi, 0);
            if (lane == r) kidx = lastI;
        }
    }
    return kidx;
}

// ---------------------------------------------------------------------------
// Kernel A: f = lrelu(LN(lrelu(LN(xyz@W0+b0))@W1+b1))  per point
// ---------------------------------------------------------------------------
__global__ void __launch_bounds__(256) kA(
    const float* __restrict__ pc,
    const float* __restrict__ W0, const float* __restrict__ b0,
    const float* __restrict__ g0, const float* __restrict__ be0,
    const float* __restrict__ W1, const float* __restrict__ b1,
    const float* __restrict__ g1, const float* __restrict__ be1)
{
    int i = blockIdx.x*256 + threadIdx.x;
    int b = i >> 10, n = i & 1023;
    const float* p = pc + (size_t)b*3072;
    float x = p[n], y = p[1024+n], z = p[2048+n];

    float t[16];
    #pragma unroll
    for (int c=0;c<16;c++)
        t[c] = fmaf(x, __ldg(&W0[c]), fmaf(y, __ldg(&W0[16+c]), fmaf(z, __ldg(&W0[32+c]), __ldg(&b0[c]))));
    {
        float m=0.f;
        #pragma unroll
        for (int c=0;c<16;c++) m += t[c];
        m *= (1.f/16.f);
        float v=0.f;
        #pragma unroll
        for (int c=0;c<16;c++){ float dd=t[c]-m; v = fmaf(dd,dd,v); }
        v *= (1.f/16.f);
        float inv = rsqrtf(v + 1e-5f);
        #pragma unroll
        for (int c=0;c<16;c++)
            t[c] = lrelu(fmaf((t[c]-m)*inv, __ldg(&g0[c]), __ldg(&be0[c])));
    }
    float u[16];
    #pragma unroll
    for (int o=0;o<16;o++){
        float a = __ldg(&b1[o]);
        #pragma unroll
        for (int c=0;c<16;c++) a = fmaf(t[c], __ldg(&W1[c*16+o]), a);
        u[o] = a;
    }
    {
        float m=0.f;
        #pragma unroll
        for (int c=0;c<16;c++) m += u[c];
        m *= (1.f/16.f);
        float v=0.f;
        #pragma unroll
        for (int c=0;c<16;c++){ float dd=u[c]-m; v = fmaf(dd,dd,v); }
        v *= (1.f/16.f);
        float inv = rsqrtf(v + 1e-5f);
        #pragma unroll
        for (int c=0;c<16;c++)
            u[c] = lrelu(fmaf((u[c]-m)*inv, __ldg(&g1[c]), __ldg(&be1[c])));
    }
    float4* o4 = reinterpret_cast<float4*>(g_feat + (size_t)i*16);
    o4[0] = make_float4(u[0],u[1],u[2],u[3]);
    o4[1] = make_float4(u[4],u[5],u[6],u[7]);
    o4[2] = make_float4(u[8],u[9],u[10],u[11]);
    o4[3] = make_float4(u[12],u[13],u[14],u[15]);
}

// ---------------------------------------------------------------------------
// Kernel B: pointconv1 (K=16 NN of 512 queries over 1024 pts) + fused squeeze
// grid (4, B): 128 queries per block, one warp per query.
// ---------------------------------------------------------------------------
__global__ void __launch_bounds__(256) kB(
    const float* __restrict__ pc,
    const float* __restrict__ Wp, const float* __restrict__ bp,
    const float* __restrict__ Ws, const float* __restrict__ bsv)
{
    __shared__ float4 sp4[1024];
    __shared__ float  sg[8][16][20];
    __shared__ float  scand[8][32];
    __shared__ int    sidxs[8][32];

    int b    = blockIdx.y;
    int base = blockIdx.x * 128;
    int tid  = threadIdx.x;
    int lane = tid & 31;
    int w    = tid >> 5;

    const float* p = pc + (size_t)b*3072;
    for (int n = tid; n < 1024; n += 256){
        float X = p[n], Y = p[1024+n], Z = p[2048+n];
        sp4[n] = make_float4(X, Y, Z, fmaf(X,X, fmaf(Y,Y, Z*Z)));
    }
    __syncthreads();

    float wr[19];
    #pragma unroll
    for (int c=0;c<19;c++) wr[c] = __ldg(&Wp[c*32 + lane]);
    float bias = __ldg(&bp[lane]);
    float wf[8], bsr[8];
    #pragma unroll
    for (int j=0;j<8;j++){ wf[j] = __ldg(&Ws[lane*8 + j]); bsr[j] = __ldg(&bsv[j]); }

    for (int m = base + w; m < base + 128; m += 8){
        int qi = 2*m;                                   // xyz1[m] == xyz0[2m]
        float4 q = sp4[qi];

        int kidx = knn16_select<32>(sp4, q.x, q.y, q.z, q.w, lane,
                                    &scand[w][0], &sidxs[w][0]);

        // --- gather neighbors into per-warp smem g[16][19] ------------------
        __syncwarp();
        if (lane < 16){
            int j = kidx;
            float4 xj = sp4[j];
            float* gr = &sg[w][lane][0];
            gr[0]=xj.x-q.x; gr[1]=xj.y-q.y; gr[2]=xj.z-q.z;
            const float4* fr = reinterpret_cast<const float4*>(g_feat + ((size_t)b*1024 + j)*16);
            float4 f0=fr[0], f1=fr[1], f2v=fr[2], f3=fr[3];
            gr[3]=f0.x;  gr[4]=f0.y;  gr[5]=f0.z;  gr[6]=f0.w;
            gr[7]=f1.x;  gr[8]=f1.y;  gr[9]=f1.z;  gr[10]=f1.w;
            gr[11]=f2v.x; gr[12]=f2v.y; gr[13]=f2v.z; gr[14]=f2v.w;
            gr[15]=f3.x; gr[16]=f3.y; gr[17]=f3.z; gr[18]=f3.w;
        }
        __syncwarp();

        // --- GEMM (lane = output channel of 32) + lrelu + maxpool ----------
        float mx = -BIGF;
        #pragma unroll 4
        for (int k=0;k<16;k++){
            const float4* gr4 = reinterpret_cast<const float4*>(&sg[w][k][0]);
            float4 v0=gr4[0], v1=gr4[1], v2=gr4[2], v3=gr4[3], v4=gr4[4];
            float a = bias;
            a = fmaf(v0.x, wr[0],  a); a = fmaf(v0.y, wr[1],  a);
            a = fmaf(v0.z, wr[2],  a); a = fmaf(v0.w, wr[3],  a);
            a = fmaf(v1.x, wr[4],  a); a = fmaf(v1.y, wr[5],  a);
            a = fmaf(v1.z, wr[6],  a); a = fmaf(v1.w, wr[7],  a);
            a = fmaf(v2.x, wr[8],  a); a = fmaf(v2.y, wr[9],  a);
            a = fmaf(v2.z, wr[10], a); a = fmaf(v2.w, wr[11], a);
            a = fmaf(v3.x, wr[12], a); a = fmaf(v3.y, wr[13], a);
            a = fmaf(v3.z, wr[14], a); a = fmaf(v3.w, wr[15], a);
            a = fmaf(v4.x, wr[16], a); a = fmaf(v4.y, wr[17], a);
            a = fmaf(v4.z, wr[18], a);
            mx = fmaxf(mx, lrelu(a));
        }

        // --- fused squeeze: fs = lrelu(mx_vec @ Ws + bs) --------------------
        float pj[8];
        #pragma unroll
        for (int j=0;j<8;j++) pj[j] = mx * wf[j];
        #pragma unroll
        for (int off=16; off>0; off>>=1){
            #pragma unroll
            for (int j=0;j<8;j++) pj[j] += __shfl_down_sync(FULLM, pj[j], off);
        }
        if (lane == 0){
            float* o = g_fs + ((size_t)b*512 + m)*8;
            #pragma unroll
            for (int j=0;j<8;j++) o[j] = lrelu(pj[j] + bsr[j]);
        }
    }
}

// ---------------------------------------------------------------------------
// Kernel C: pointconv2 (128 queries, 512 candidates, 11ch -> 128ch),
// fused column-sum (mean commutes with the final linear map).
// grid (2, B): 64 queries per block, one warp per query.
// ---------------------------------------------------------------------------
__global__ void __launch_bounds__(256) kC(
    const float* __restrict__ pc,
    const float* __restrict__ Wc, const float* __restrict__ bc)
{
    __shared__ float4 sp4[512];
    __shared__ float  sf[512*8];
    __shared__ float  sg[8][16][12];
    __shared__ float  scand[8][32];
    __shared__ int    sidxs[8][32];
    __shared__ float  sacc[8][128];

    int b    = blockIdx.y;
    int base = blockIdx.x * 64;
    int tid  = threadIdx.x;
    int lane = tid & 31;
    int w    = tid >> 5;

    const float* p = pc + (size_t)b*3072;
    for (int m = tid; m < 512; m += 256){
        float X = p[2*m], Y = p[1024+2*m], Z = p[2048+2*m]; // xyz1[m]=xyz0[2m]
        sp4[m] = make_float4(X, Y, Z, fmaf(X,X, fmaf(Y,Y, Z*Z)));
    }
    {
        const float4* src = reinterpret_cast<const float4*>(g_fs + (size_t)b*4096);
        float4* dst = reinterpret_cast<float4*>(sf);
        for (int t = tid; t < 1024; t += 256) dst[t] = src[t];
    }
    __syncthreads();

    float wc0[11], wc1[11], wc2[11], wc3[11];
    #pragma unroll
    for (int c=0;c<11;c++){
        wc0[c] = __ldg(&Wc[c*128 + lane]);
        wc1[c] = __ldg(&Wc[c*128 + lane + 32]);
        wc2[c] = __ldg(&Wc[c*128 + lane + 64]);
        wc3[c] = __ldg(&Wc[c*128 + lane + 96]);
    }
    float bc0 = __ldg(&bc[lane]),    bc1 = __ldg(&bc[lane+32]);
    float bc2 = __ldg(&bc[lane+64]), bc3 = __ldg(&bc[lane+96]);

    float acc0 = 0.f, acc1 = 0.f, acc2 = 0.f, acc3 = 0.f;

    for (int m2 = base + w; m2 < base + 64; m2 += 8){
        int qi = 4*m2;                                  // xyz2[m2] == xyz1[4*m2]
        float4 q = sp4[qi];

        int kidx = knn16_select<16>(sp4, q.x, q.y, q.z, q.w, lane,
                                    &scand[w][0], &sidxs[w][0]);

        __syncwarp();
        if (lane < 16){
            int j = kidx;
            float4 xj = sp4[j];
            float* gr = &sg[w][lane][0];
            gr[0]=xj.x-q.x; gr[1]=xj.y-q.y; gr[2]=xj.z-q.z;
            const float4* fr = reinterpret_cast<const float4*>(sf + j*8);
            float4 f0=fr[0], f1=fr[1];
            gr[3]=f0.x; gr[4]=f0.y; gr[5]=f0.z; gr[6]=f0.w;
            gr[7]=f1.x; gr[8]=f1.y; gr[9]=f1.z; gr[10]=f1.w;
        }
        __syncwarp();

        float mx0=-BIGF, mx1=-BIGF, mx2=-BIGF, mx3=-BIGF;
        #pragma unroll 4
        for (int k=0;k<16;k++){
            const float4* gr4 = reinterpret_cast<const float4*>(&sg[w][k][0]);
            float4 v0=gr4[0], v1=gr4[1], v2=gr4[2];
            float gv[11] = {v0.x,v0.y,v0.z,v0.w, v1.x,v1.y,v1.z,v1.w, v2.x,v2.y,v2.z};
            float a0=bc0, a1=bc1, a2=bc2, a3=bc3;
            #pragma unroll
            for (int c=0;c<11;c++){
                a0 = fmaf(gv[c], wc0[c], a0);
                a1 = fmaf(gv[c], wc1[c], a1);
                a2 = fmaf(gv[c], wc2[c], a2);
                a3 = fmaf(gv[c], wc3[c], a3);
            }
            mx0 = fmaxf(mx0, lrelu(a0));
            mx1 = fmaxf(mx1, lrelu(a1));
            mx2 = fmaxf(mx2, lrelu(a2));
            mx3 = fmaxf(mx3, lrelu(a3));
        }
        acc0 += mx0; acc1 += mx1; acc2 += mx2; acc3 += mx3;
    }

    // deterministic in-block reduction of per-warp partial sums
    sacc[w][lane]    = acc0;
    sacc[w][lane+32] = acc1;
    sacc[w][lane+64] = acc2;
    sacc[w][lane+96] = acc3;
    __syncthreads();
    if (tid < 128){
        float s = sacc[0][tid];
        #pragma unroll
        for (int ww=1; ww<8; ww++) s += sacc[ww][tid];
        g_psum[((size_t)b*2 + blockIdx.x)*128 + tid] = s;
    }
}

// ---------------------------------------------------------------------------
// Kernel D: out[b] = (psum0+psum1)/128 @ We + be
// ---------------------------------------------------------------------------
__global__ void __launch_bounds__(256) kD(
    const float* __restrict__ We, const float* __restrict__ be,
    float* __restrict__ out)
{
    __shared__ float sbar[128];
    int b = blockIdx.x, tid = threadIdx.x;
    if (tid < 128){
        float s = g_psum[((size_t)b*2)*128 + tid] + g_psum[((size_t)b*2+1)*128 + tid];
        sbar[tid] = s * (1.f/128.f);
    }
    __syncthreads();
    float acc = __ldg(&be[tid]);
    #pragma unroll 8
    for (int c=0;c<128;c++) acc = fmaf(sbar[c], __ldg(&We[c*256 + tid]), acc);
    out[(size_t)b*256 + tid] = acc;
}

// ---------------------------------------------------------------------------
extern "C" void kernel_launch(void* const* d_in, const int* in_sizes, int n_in,
                              void* d_out, int out_size)
{
    (void)in_sizes; (void)n_in; (void)out_size;
    const float* pc  = (const float*)d_in[0];
    const float* W0  = (const float*)d_in[1];
    const float* b0  = (const float*)d_in[2];
    const float* g0  = (const float*)d_in[3];
    const float* be0 = (const float*)d_in[4];
    const float* W1  = (const float*)d_in[5];
    const float* b1  = (const float*)d_in[6];
    const float* g1  = (const float*)d_in[7];
    const float* be1 = (const float*)d_in[8];
    const float* Wp  = (const float*)d_in[9];
    const float* bp  = (const float*)d_in[10];
    const float* Ws  = (const float*)d_in[11];
    const float* bsv = (const float*)d_in[12];
    const float* Wc  = (const float*)d_in[13];
    const float* bc  = (const float*)d_in[14];
    const float* We  = (const float*)d_in[15];
    const float* be  = (const float*)d_in[16];
    float* out = (float*)d_out;

    kA<<<1024, 256>>>(pc, W0, b0, g0, be0, W1, b1, g1, be1);
    dim3 gB(4, 256);
    kB<<<gB, 256>>>(pc, Wp, bp, Ws, bsv);
    dim3 gC(2, 256);
    kC<<<gC, 256>>>(pc, Wc, bc);
    kD<<<256, 256>>>(We, be, out);
}

// round 4
// speedup vs baseline: 3.4340x; 1.1160x over previous
#include <cuda_runtime.h>
#include <cstdint>

#define FULLM 0xFFFFFFFFu
#define BIGF  3.402823466e+38f

__device__ float g_feat[256*1024*16]; // stage-1 per-point features (B,N,16)
__device__ float g_fs[256*512*8];     // squeezed features on xyz1 (B,512,8)
__device__ float g_psum[256*2*128];   // per-block partial sums of f2 (B,2,128)

__device__ __forceinline__ float lrelu(float x){ return x > 0.f ? x : 0.2f*x; }

// ---- packed f32x2 helpers (Blackwell) -------------------------------------
__device__ __forceinline__ unsigned long long pk(float lo, float hi){
    unsigned long long r;
    asm("mov.b64 %0, {%1, %2};" : "=l"(r) : "f"(lo), "f"(hi));
    return r;
}
__device__ __forceinline__ float2 upk(unsigned long long v){
    float2 r;
    asm("mov.b64 {%0, %1}, %2;" : "=f"(r.x), "=f"(r.y) : "l"(v));
    return r;
}
__device__ __forceinline__ unsigned long long ffma2(
    unsigned long long a, unsigned long long b, unsigned long long c){
    unsigned long long d;
    asm("fma.rn.f32x2 %0, %1, %2, %3;" : "=l"(d) : "l"(a), "l"(b), "l"(c));
    return d;
}

// Value-only bitonic sort of 32 floats across a warp (ascending).
__device__ __forceinline__ float bsort32_val(float s, int lane){
    #pragma unroll
    for (int k = 2; k <= 32; k <<= 1){
        #pragma unroll
        for (int j = k >> 1; j > 0; j >>= 1){
            float o = __shfl_xor_sync(FULLM, s, j);
            bool keepmin = ((lane & j) == 0) == ((lane & k) == 0);
            float mn = fminf(s, o), mx = fmaxf(s, o);
            s = keepmin ? mn : mx;
        }
    }
    return s;
}

// Bitonic sort of 32 (d,i) pairs across a warp, ascending lex (d, then i).
__device__ __forceinline__ void bsort32_pair(float& d, int& i, int lane){
    #pragma unroll
    for (int k = 2; k <= 32; k <<= 1){
        #pragma unroll
        for (int j = k >> 1; j > 0; j >>= 1){
            float od = __shfl_xor_sync(FULLM, d, j);
            int   oi = __shfl_xor_sync(FULLM, i, j);
            bool lower = (lane & j) == 0;
            bool asc   = (lane & k) == 0;
            bool osm   = (od < d) || (od == d && oi < i);
            bool take  = (lower == asc) ? osm : !osm;
            if (take){ d = od; i = oi; }
        }
    }
}

// Exact top-16 of NT*32 candidates. sp holds (x,y,z,|p|^2) per point.
// Returns the set of 16 nearest indices distributed on lanes 0..15
// (arbitrary order — callers only max-pool over the set).
template<int NT>
__device__ __forceinline__ int knn16_select(
    const float4* __restrict__ sp,
    float qx, float qy, float qz, float qn2, int lane,
    float* scand, int* sidxs)
{
    // --- phase 1: compute & register-cache all NT distances ----------------
    float d[NT];
    #pragma unroll
    for (int t = 0; t < NT; t++){
        float4 v = sp[lane + t*32];
        float dot = fmaf(qx, v.x, fmaf(qy, v.y, qz*v.z));
        d[t] = fmaf(-2.f, dot, qn2 + v.w);
    }
    float m0 = d[0], m1 = d[1], m2 = d[2], m3 = d[3];
    #pragma unroll
    for (int t = 4; t < NT; t += 4){
        m0 = fminf(m0, d[t]);   m1 = fminf(m1, d[t+1]);
        m2 = fminf(m2, d[t+2]); m3 = fminf(m3, d[t+3]);
    }
    float bd = fminf(fminf(m0, m1), fminf(m2, m3));

    // --- phase 2: threshold = 16th-smallest lane minimum (valid bound) -----
    float thr = __shfl_sync(FULLM, bsort32_val(bd, lane), 15);

    // --- phase 3: ballot-compact all d <= thr into 32-slot buffer ----------
    scand[lane] = BIGF; sidxs[lane] = 0x7FFFFFFF;
    __syncwarp();
    unsigned lt = (1u << lane) - 1u;
    int cnt = 0;
    #pragma unroll
    for (int t = 0; t < NT; t++){
        bool p = (d[t] <= thr);
        unsigned mask = __ballot_sync(FULLM, p);
        if (p){
            int pos = cnt + __popc(mask & lt);
            if (pos < 32){ scand[pos] = d[t]; sidxs[pos] = lane + t*32; }
        }
        cnt += __popc(mask);
    }
    __syncwarp();

    int kidx;
    if (cnt <= 32){
        float d2 = scand[lane]; int i2 = sidxs[lane];
        // value-only sort to find the 16th-smallest distance in the buffer
        float thr16 = __shfl_sync(FULLM, bsort32_val(d2, lane), 15);
        unsigned sel = __ballot_sync(FULLM, d2 <= thr16);
        if (__popc(sel) == 16){
            // no boundary tie: selected lanes ARE the exact top-16 set
            __syncwarp();
            if (d2 <= thr16){
                int pos = __popc(sel & lt);
                sidxs[pos] = i2;
            }
            __syncwarp();
            kidx = sidxs[lane];
        } else {
            // boundary tie on distance: exact lex (d, idx) sort
            bsort32_pair(d2, i2, lane);
            kidx = i2;
        }
    } else {
        // --- rare fallback: progressive argmin with lex exclusion ----------
        float lastD = -BIGF; int lastI = -1; kidx = 0x7FFFFFFF;
        for (int r = 0; r < 16; r++){
            float cbd = BIGF; int cbi = 0x7FFFFFFF;
            #pragma unroll
            for (int t = 0; t < NT; t++){
                int j = lane + t*32;
                bool gt = (d[t] > lastD) || (d[t] == lastD && j > lastI);
                if (gt && ((d[t] < cbd) || (d[t] == cbd && j < cbi))){ cbd = d[t]; cbi = j; }
            }
            #pragma unroll
            for (int off = 16; off > 0; off >>= 1){
                float od = __shfl_down_sync(FULLM, cbd, off);
                int   oi = __shfl_down_sync(FULLM, cbi, off);
                if (od < cbd || (od == cbd && oi < cbi)){ cbd = od; cbi = oi; }
            }
            lastD = __shfl_sync(FULLM, cbd, 0);
            lastI = __shfl_sync(FULLM, cbi, 0);
            if (lane == r) kidx = lastI;
        }
    }
    return kidx;
}

// ---------------------------------------------------------------------------
// Kernel A: f = lrelu(LN(lrelu(LN(xyz@W0+b0))@W1+b1))  per point
// ---------------------------------------------------------------------------
__global__ void __launch_bounds__(256) kA(
    const float* __restrict__ pc,
    const float* __restrict__ W0, const float* __restrict__ b0,
    const float* __restrict__ g0, const float* __restrict__ be0,
    const float* __restrict__ W1, const float* __restrict__ b1,
    const float* __restrict__ g1, const float* __restrict__ be1)
{
    int i = blockIdx.x*256 + threadIdx.x;
    int b = i >> 10, n = i & 1023;
    const float* p = pc + (size_t)b*3072;
    float x = p[n], y = p[1024+n], z = p[2048+n];

    float t[16];
    #pragma unroll
    for (int c=0;c<16;c++)
        t[c] = fmaf(x, __ldg(&W0[c]), fmaf(y, __ldg(&W0[16+c]), fmaf(z, __ldg(&W0[32+c]), __ldg(&b0[c]))));
    {
        float m=0.f;
        #pragma unroll
        for (int c=0;c<16;c++) m += t[c];
        m *= (1.f/16.f);
        float v=0.f;
        #pragma unroll
        for (int c=0;c<16;c++){ float dd=t[c]-m; v = fmaf(dd,dd,v); }
        v *= (1.f/16.f);
        float inv = rsqrtf(v + 1e-5f);
        #pragma unroll
        for (int c=0;c<16;c++)
            t[c] = lrelu(fmaf((t[c]-m)*inv, __ldg(&g0[c]), __ldg(&be0[c])));
    }
    float u[16];
    #pragma unroll
    for (int o=0;o<16;o++){
        float a = __ldg(&b1[o]);
        #pragma unroll
        for (int c=0;c<16;c++) a = fmaf(t[c], __ldg(&W1[c*16+o]), a);
        u[o] = a;
    }
    {
        float m=0.f;
        #pragma unroll
        for (int c=0;c<16;c++) m += u[c];
        m *= (1.f/16.f);
        float v=0.f;
        #pragma unroll
        for (int c=0;c<16;c++){ float dd=u[c]-m; v = fmaf(dd,dd,v); }
        v *= (1.f/16.f);
        float inv = rsqrtf(v + 1e-5f);
        #pragma unroll
        for (int c=0;c<16;c++)
            u[c] = lrelu(fmaf((u[c]-m)*inv, __ldg(&g1[c]), __ldg(&be1[c])));
    }
    float4* o4 = reinterpret_cast<float4*>(g_feat + (size_t)i*16);
    o4[0] = make_float4(u[0],u[1],u[2],u[3]);
    o4[1] = make_float4(u[4],u[5],u[6],u[7]);
    o4[2] = make_float4(u[8],u[9],u[10],u[11]);
    o4[3] = make_float4(u[12],u[13],u[14],u[15]);
}

// ---------------------------------------------------------------------------
// Kernel B: pointconv1 (K=16 NN of 512 queries over 1024 pts) + fused squeeze
// grid (4, B): 128 queries per block, one warp per query.
// ---------------------------------------------------------------------------
__global__ void __launch_bounds__(256) kB(
    const float* __restrict__ pc,
    const float* __restrict__ Wp, const float* __restrict__ bp,
    const float* __restrict__ Ws, const float* __restrict__ bsv)
{
    __shared__ __align__(16) float4 sp4[1024];
    __shared__ __align__(16) float  sg[8][16][20];
    __shared__ float  scand[8][32];
    __shared__ int    sidxs[8][32];
    __shared__ __align__(16) float  smx[8][32];

    int b    = blockIdx.y;
    int base = blockIdx.x * 128;
    int tid  = threadIdx.x;
    int lane = tid & 31;
    int w    = tid >> 5;

    const float* p = pc + (size_t)b*3072;
    for (int n = tid; n < 1024; n += 256){
        float X = p[n], Y = p[1024+n], Z = p[2048+n];
        sp4[n] = make_float4(X, Y, Z, fmaf(X,X, fmaf(Y,Y, Z*Z)));
    }
    __syncthreads();

    // packed per-lane GEMM weights: lane = output channel
    unsigned long long wp[9];
    #pragma unroll
    for (int c=0;c<9;c++)
        wp[c] = pk(__ldg(&Wp[(2*c)*32 + lane]), __ldg(&Wp[(2*c+1)*32 + lane]));
    float wr18 = __ldg(&Wp[18*32 + lane]);
    unsigned long long accp = pk(__ldg(&bp[lane]), 0.f);

    // squeeze weights: lane handles output j = lane&7 over c in [cb, cb+8)
    int jq = lane & 7, cb = (lane >> 3) * 8;
    unsigned long long wsp[4];
    #pragma unroll
    for (int i=0;i<4;i++)
        wsp[i] = pk(__ldg(&Ws[(cb+2*i)*8 + jq]), __ldg(&Ws[(cb+2*i+1)*8 + jq]));
    float bsq = __ldg(&bsv[jq]);

    for (int m = base + w; m < base + 128; m += 8){
        int qi = 2*m;                                   // xyz1[m] == xyz0[2m]
        float4 q = sp4[qi];

        int kidx = knn16_select<32>(sp4, q.x, q.y, q.z, q.w, lane,
                                    &scand[w][0], &sidxs[w][0]);

        // --- gather neighbors into per-warp smem g[16][19] ------------------
        __syncwarp();
        if (lane < 16){
            int j = kidx;
            float4 xj = sp4[j];
            float* gr = &sg[w][lane][0];
            gr[0]=xj.x-q.x; gr[1]=xj.y-q.y; gr[2]=xj.z-q.z;
            const float4* fr = reinterpret_cast<const float4*>(g_feat + ((size_t)b*1024 + j)*16);
            float4 f0=fr[0], f1=fr[1], f2v=fr[2], f3=fr[3];
            gr[3]=f0.x;  gr[4]=f0.y;  gr[5]=f0.z;  gr[6]=f0.w;
            gr[7]=f1.x;  gr[8]=f1.y;  gr[9]=f1.z;  gr[10]=f1.w;
            gr[11]=f2v.x; gr[12]=f2v.y; gr[13]=f2v.z; gr[14]=f2v.w;
            gr[15]=f3.x; gr[16]=f3.y; gr[17]=f3.z; gr[18]=f3.w;
        }
        __syncwarp();

        // --- GEMM (lane = output channel) via packed FFMA2 + maxpool -------
        float mx = -BIGF;
        #pragma unroll 4
        for (int k=0;k<16;k++){
            const float* gr = &sg[w][k][0];
            ulonglong2 pA = *reinterpret_cast<const ulonglong2*>(gr);
            ulonglong2 pB = *reinterpret_cast<const ulonglong2*>(gr+4);
            ulonglong2 pC = *reinterpret_cast<const ulonglong2*>(gr+8);
            ulonglong2 pD = *reinterpret_cast<const ulonglong2*>(gr+12);
            float2 tl = *reinterpret_cast<const float2*>(gr+16);
            float  g18 = gr[18];
            unsigned long long acc = accp;
            acc = ffma2(pA.x, wp[0], acc);
            acc = ffma2(pA.y, wp[1], acc);
            acc = ffma2(pB.x, wp[2], acc);
            acc = ffma2(pB.y, wp[3], acc);
            acc = ffma2(pC.x, wp[4], acc);
            acc = ffma2(pC.y, wp[5], acc);
            acc = ffma2(pD.x, wp[6], acc);
            acc = ffma2(pD.y, wp[7], acc);
            acc = ffma2(pk(tl.x, tl.y), wp[8], acc);
            float2 s = upk(acc);
            float a = fmaf(g18, wr18, s.x + s.y);
            mx = fmaxf(mx, lrelu(a));
        }

        // --- fused squeeze via smem transpose: fs = lrelu(mx @ Ws + bs) -----
        smx[w][lane] = mx;
        __syncwarp();
        const unsigned long long* mp =
            reinterpret_cast<const unsigned long long*>(&smx[w][cb]);
        unsigned long long s2 = pk(0.f, 0.f);
        s2 = ffma2(mp[0], wsp[0], s2);
        s2 = ffma2(mp[1], wsp[1], s2);
        s2 = ffma2(mp[2], wsp[2], s2);
        s2 = ffma2(mp[3], wsp[3], s2);
        float2 sv = upk(s2);
        float s = sv.x + sv.y;
        s += __shfl_down_sync(FULLM, s, 16);
        s += __shfl_down_sync(FULLM, s, 8);
        if (lane < 8)
            g_fs[((size_t)b*512 + m)*8 + jq] = lrelu(s + bsq);
    }
}

// ---------------------------------------------------------------------------
// Kernel C: pointconv2 (128 queries, 512 candidates, 11ch -> 128ch),
// fused column-sum (mean commutes with the final linear map).
// grid (2, B): 64 queries per block, one warp per query.
// ---------------------------------------------------------------------------
__global__ void __launch_bounds__(256) kC(
    const float* __restrict__ pc,
    const float* __restrict__ Wc, const float* __restrict__ bc)
{
    __shared__ __align__(16) float4 sp4[512];
    __shared__ __align__(16) float  sf[512*8];
    __shared__ __align__(16) float  sg[8][16][12];
    __shared__ float  scand[8][32];
    __shared__ int    sidxs[8][32];
    __shared__ float  sacc[8][128];

    int b    = blockIdx.y;
    int base = blockIdx.x * 64;
    int tid  = threadIdx.x;
    int lane = tid & 31;
    int w    = tid >> 5;

    const float* p = pc + (size_t)b*3072;
    for (int m = tid; m < 512; m += 256){
        float X = p[2*m], Y = p[1024+2*m], Z = p[2048+2*m]; // xyz1[m]=xyz0[2m]
        sp4[m] = make_float4(X, Y, Z, fmaf(X,X, fmaf(Y,Y, Z*Z)));
    }
    {
        const float4* src = reinterpret_cast<const float4*>(g_fs + (size_t)b*4096);
        float4* dst = reinterpret_cast<float4*>(sf);
        for (int t = tid; t < 1024; t += 256) dst[t] = src[t];
    }
    __syncthreads();

    // packed weights for 4 output channels per lane (lane, lane+32, +64, +96)
    unsigned long long wq0[5], wq1[5], wq2[5], wq3[5];
    #pragma unroll
    for (int c=0;c<5;c++){
        wq0[c] = pk(__ldg(&Wc[(2*c)*128 + lane]),      __ldg(&Wc[(2*c+1)*128 + lane]));
        wq1[c] = pk(__ldg(&Wc[(2*c)*128 + lane + 32]), __ldg(&Wc[(2*c+1)*128 + lane + 32]));
        wq2[c] = pk(__ldg(&Wc[(2*c)*128 + lane + 64]), __ldg(&Wc[(2*c+1)*128 + lane + 64]));
        wq3[c] = pk(__ldg(&Wc[(2*c)*128 + lane + 96]), __ldg(&Wc[(2*c+1)*128 + lane + 96]));
    }
    float w10_0 = __ldg(&Wc[10*128 + lane]),      w10_1 = __ldg(&Wc[10*128 + lane + 32]);
    float w10_2 = __ldg(&Wc[10*128 + lane + 64]), w10_3 = __ldg(&Wc[10*128 + lane + 96]);
    unsigned long long bp0 = pk(__ldg(&bc[lane]),     0.f);
    unsigned long long bp1 = pk(__ldg(&bc[lane+32]),  0.f);
    unsigned long long bp2 = pk(__ldg(&bc[lane+64]),  0.f);
    unsigned long long bp3 = pk(__ldg(&bc[lane+96]),  0.f);

    float acc0 = 0.f, acc1 = 0.f, acc2 = 0.f, acc3 = 0.f;

    for (int m2 = base + w; m2 < base + 64; m2 += 8){
        int qi = 4*m2;                                  // xyz2[m2] == xyz1[4*m2]
        float4 q = sp4[qi];

        int kidx = knn16_select<16>(sp4, q.x, q.y, q.z, q.w, lane,
                                    &scand[w][0], &sidxs[w][0]);

        __syncwarp();
        if (lane < 16){
            int j = kidx;
            float4 xj = sp4[j];
            float* gr = &sg[w][lane][0];
            gr[0]=xj.x-q.x; gr[1]=xj.y-q.y; gr[2]=xj.z-q.z;
            const float4* fr = reinterpret_cast<const float4*>(sf + j*8);
            float4 f0=fr[0], f1=fr[1];
            gr[3]=f0.x; gr[4]=f0.y; gr[5]=f0.z; gr[6]=f0.w;
            gr[7]=f1.x; gr[8]=f1.y; gr[9]=f1.z; gr[10]=f1.w;
        }
        __syncwarp();

        float mx0=-BIGF, mx1=-BIGF, mx2=-BIGF, mx3=-BIGF;
        #pragma unroll 4
        for (int k=0;k<16;k++){
            const float* gr = &sg[w][k][0];
            ulonglong2 pA = *reinterpret_cast<const ulonglong2*>(gr);     // g0..g3
            ulonglong2 pB = *reinterpret_cast<const ulonglong2*>(gr+4);   // g4..g7
            float4     v2 = *reinterpret_cast<const float4*>(gr+8);       // g8..g11(pad)
            unsigned long long p4 = pk(v2.x, v2.y);
            float g10 = v2.z;
            unsigned long long a0=bp0, a1=bp1, a2=bp2, a3=bp3;
            a0 = ffma2(pA.x, wq0[0], a0); a1 = ffma2(pA.x, wq1[0], a1);
            a2 = ffma2(pA.x, wq2[0], a2); a3 = ffma2(pA.x, wq3[0], a3);
            a0 = ffma2(pA.y, wq0[1], a0); a1 = ffma2(pA.y, wq1[1], a1);
            a2 = ffma2(pA.y, wq2[1], a2); a3 = ffma2(pA.y, wq3[1], a3);
            a0 = ffma2(pB.x, wq0[2], a0); a1 = ffma2(pB.x, wq1[2], a1);
            a2 = ffma2(pB.x, wq2[2], a2); a3 = ffma2(pB.x, wq3[2], a3);
            a0 = ffma2(pB.y, wq0[3], a0); a1 = ffma2(pB.y, wq1[3], a1);
            a2 = ffma2(pB.y, wq2[3], a2); a3 = ffma2(pB.y, wq3[3], a3);
            a0 = ffma2(p4,   wq0[4], a0); a1 = ffma2(p4,   wq1[4], a1);
            a2 = ffma2(p4,   wq2[4], a2); a3 = ffma2(p4,   wq3[4], a3);
            float2 s0 = upk(a0), s1 = upk(a1), s2 = upk(a2), s3 = upk(a3);
            float r0 = fmaf(g10, w10_0, s0.x + s0.y);
            float r1 = fmaf(g10, w10_1, s1.x + s1.y);
            float r2 = fmaf(g10, w10_2, s2.x + s2.y);
            float r3 = fmaf(g10, w10_3, s3.x + s3.y);
            mx0 = fmaxf(mx0, lrelu(r0));
            mx1 = fmaxf(mx1, lrelu(r1));
            mx2 = fmaxf(mx2, lrelu(r2));
            mx3 = fmaxf(mx3, lrelu(r3));
        }
        acc0 += mx0; acc1 += mx1; acc2 += mx2; acc3 += mx3;
    }

    // deterministic in-block reduction of per-warp partial sums
    sacc[w][lane]    = acc0;
    sacc[w][lane+32] = acc1;
    sacc[w][lane+64] = acc2;
    sacc[w][lane+96] = acc3;
    __syncthreads();
    if (tid < 128){
        float s = sacc[0][tid];
        #pragma unroll
        for (int ww=1; ww<8; ww++) s += sacc[ww][tid];
        g_psum[((size_t)b*2 + blockIdx.x)*128 + tid] = s;
    }
}

// ---------------------------------------------------------------------------
// Kernel D: out[b] = (psum0+psum1)/128 @ We + be
// ---------------------------------------------------------------------------
__global__ void __launch_bounds__(256) kD(
    const float* __restrict__ We, const float* __restrict__ be,
    float* __restrict__ out)
{
    __shared__ float sbar[128];
    int b = blockIdx.x, tid = threadIdx.x;
    if (tid < 128){
        float s = g_psum[((size_t)b*2)*128 + tid] + g_psum[((size_t)b*2+1)*128 + tid];
        sbar[tid] = s * (1.f/128.f);
    }
    __syncthreads();
    float acc = __ldg(&be[tid]);
    #pragma unroll 8
    for (int c=0;c<128;c++) acc = fmaf(sbar[c], __ldg(&We[c*256 + tid]), acc);
    out[(size_t)b*256 + tid] = acc;
}

// ---------------------------------------------------------------------------
extern "C" void kernel_launch(void* const* d_in, const int* in_sizes, int n_in,
                              void* d_out, int out_size)
{
    (void)in_sizes; (void)n_in; (void)out_size;
    const float* pc  = (const float*)d_in[0];
    const float* W0  = (const float*)d_in[1];
    const float* b0  = (const float*)d_in[2];
    const float* g0  = (const float*)d_in[3];
    const float* be0 = (const float*)d_in[4];
    const float* W1  = (const float*)d_in[5];
    const float* b1  = (const float*)d_in[6];
    const float* g1  = (const float*)d_in[7];
    const float* be1 = (const float*)d_in[8];
    const float* Wp  = (const float*)d_in[9];
    const float* bp  = (const float*)d_in[10];
    const float* Ws  = (const float*)d_in[11];
    const float* bsv = (const float*)d_in[12];
    const float* Wc  = (const float*)d_in[13];
    const float* bc  = (const float*)d_in[14];
    const float* We  = (const float*)d_in[15];
    const float* be  = (const float*)d_in[16];
    float* out = (float*)d_out;

    kA<<<1024, 256>>>(pc, W0, b0, g0, be0, W1, b1, g1, be1);
    dim3 gB(4, 256);
    kB<<<gB, 256>>>(pc, Wp, bp, Ws, bsv);
    dim3 gC(2, 256);
    kC<<<gC, 256>>>(pc, Wc, bc);
    kD<<<256, 256>>>(We, be, out);
}

// round 5
// speedup vs baseline: 3.6155x; 1.0528x over previous
#include <cuda_runtime.h>
#include <cstdint>

#define FULLM 0xFFFFFFFFu
#define BIGF  3.402823466e+38f

__device__ float g_feat[256*1024*16]; // stage-1 per-point features (B,N,16)
__device__ float g_fs[256*512*8];     // squeezed features on xyz1 (B,512,8)
__device__ float g_psum[256*2*128];   // per-block partial sums of f2 (B,2,128)

__device__ __forceinline__ float lrelu(float x){ return x > 0.f ? x : 0.2f*x; }

// ---- packed f32x2 helpers (Blackwell) -------------------------------------
__device__ __forceinline__ unsigned long long pk(float lo, float hi){
    unsigned long long r;
    asm("mov.b64 %0, {%1, %2};" : "=l"(r) : "f"(lo), "f"(hi));
    return r;
}
__device__ __forceinline__ float2 upk(unsigned long long v){
    float2 r;
    asm("mov.b64 {%0, %1}, %2;" : "=f"(r.x), "=f"(r.y) : "l"(v));
    return r;
}
__device__ __forceinline__ unsigned long long ffma2(
    unsigned long long a, unsigned long long b, unsigned long long c){
    unsigned long long d;
    asm("fma.rn.f32x2 %0, %1, %2, %3;" : "=l"(d) : "l"(a), "l"(b), "l"(c));
    return d;
}

__device__ __forceinline__ float qdist(const float4& v, float qx, float qy, float qz){
    // d' = |p|^2 - 2 q.p  (query-constant |q|^2 dropped: order-preserving)
    return fmaf(-2.f, fmaf(qx, v.x, fmaf(qy, v.y, qz*v.z)), v.w);
}

// Value-only bitonic sort of 32 floats across a warp (ascending).
__device__ __forceinline__ float bsort32_val(float s, int lane){
    #pragma unroll
    for (int k = 2; k <= 32; k <<= 1){
        #pragma unroll
        for (int j = k >> 1; j > 0; j >>= 1){
            float o = __shfl_xor_sync(FULLM, s, j);
            bool keepmin = ((lane & j) == 0) == ((lane & k) == 0);
            float mn = fminf(s, o), mx = fmaxf(s, o);
            s = keepmin ? mn : mx;
        }
    }
    return s;
}

// Bitonic sort of 32 (d,i) pairs across a warp, ascending lex (d, then i).
__device__ __forceinline__ void bsort32_pair(float& d, int& i, int lane){
    #pragma unroll
    for (int k = 2; k <= 32; k <<= 1){
        #pragma unroll
        for (int j = k >> 1; j > 0; j >>= 1){
            float od = __shfl_xor_sync(FULLM, d, j);
            int   oi = __shfl_xor_sync(FULLM, i, j);
            bool lower = (lane & j) == 0;
            bool asc   = (lane & k) == 0;
            bool osm   = (od < d) || (od == d && oi < i);
            bool take  = (lower == asc) ? osm : !osm;
            if (take){ d = od; i = oi; }
        }
    }
}

// Exact top-16 of NT*32 candidates. sp holds (x,y,z,|p|^2) per point.
// Returns the set of 16 nearest indices distributed on lanes 0..15
// (arbitrary order — callers only max-pool over the set).
// Distances recomputed per pass (register-light for occupancy).
template<int NT>
__device__ __forceinline__ int knn16_select(
    const float4* __restrict__ sp,
    float qx, float qy, float qz, int lane,
    float* scand, int* sidxs)
{
    // --- phase 1: per-lane min distance (4 independent chains) -------------
    float m0 = BIGF, m1 = BIGF, m2 = BIGF, m3 = BIGF;
    #pragma unroll
    for (int t = 0; t < NT; t += 4){
        float d0 = qdist(sp[lane + (t  )*32], qx, qy, qz);
        float d1 = qdist(sp[lane + (t+1)*32], qx, qy, qz);
        float d2 = qdist(sp[lane + (t+2)*32], qx, qy, qz);
        float d3 = qdist(sp[lane + (t+3)*32], qx, qy, qz);
        m0 = fminf(m0, d0); m1 = fminf(m1, d1);
        m2 = fminf(m2, d2); m3 = fminf(m3, d3);
    }
    float bd = fminf(fminf(m0, m1), fminf(m2, m3));

    // --- phase 2: threshold = 16th-smallest lane minimum (valid bound) -----
    float thr = __shfl_sync(FULLM, bsort32_val(bd, lane), 15);

    // --- phase 3: recompute + ballot-compact all d <= thr ------------------
    scand[lane] = BIGF; sidxs[lane] = 0x7FFFFFFF;
    __syncwarp();
    unsigned lt = (1u << lane) - 1u;
    int cnt = 0;
    #pragma unroll
    for (int t = 0; t < NT; t++){
        float d = qdist(sp[lane + t*32], qx, qy, qz);
        bool p = (d <= thr);
        unsigned mask = __ballot_sync(FULLM, p);
        if (p){
            int pos = cnt + __popc(mask & lt);
            if (pos < 32){ scand[pos] = d; sidxs[pos] = lane + t*32; }
        }
        cnt += __popc(mask);
    }
    __syncwarp();

    int kidx;
    if (cnt <= 32){
        float d2 = scand[lane]; int i2 = sidxs[lane];
        // value-only sort to find the 16th-smallest distance in the buffer
        float thr16 = __shfl_sync(FULLM, bsort32_val(d2, lane), 15);
        unsigned sel = __ballot_sync(FULLM, d2 <= thr16);
        if (__popc(sel) == 16){
            // no boundary tie: selected lanes ARE the exact top-16 set
            __syncwarp();
            if (d2 <= thr16){
                int pos = __popc(sel & lt);
                sidxs[pos] = i2;
            }
            __syncwarp();
            kidx = sidxs[lane];
        } else {
            // boundary tie on distance: exact lex (d, idx) sort
            bsort32_pair(d2, i2, lane);
            kidx = i2;
        }
    } else {
        // --- rare fallback: progressive argmin with lex exclusion ----------
        float lastD = -BIGF; int lastI = -1; kidx = 0x7FFFFFFF;
        for (int r = 0; r < 16; r++){
            float cbd = BIGF; int cbi = 0x7FFFFFFF;
            #pragma unroll
            for (int t = 0; t < NT; t++){
                int j = lane + t*32;
                float d = qdist(sp[j], qx, qy, qz);
                bool gt = (d > lastD) || (d == lastD && j > lastI);
                if (gt && ((d < cbd) || (d == cbd && j < cbi))){ cbd = d; cbi = j; }
            }
            #pragma unroll
            for (int off = 16; off > 0; off >>= 1){
                float od = __shfl_down_sync(FULLM, cbd, off);
                int   oi = __shfl_down_sync(FULLM, cbi, off);
                if (od < cbd || (od == cbd && oi < cbi)){ cbd = od; cbi = oi; }
            }
            lastD = __shfl_sync(FULLM, cbd, 0);
            lastI = __shfl_sync(FULLM, cbi, 0);
            if (lane == r) kidx = lastI;
        }
    }
    return kidx;
}

// ---------------------------------------------------------------------------
// Kernel A: f = lrelu(LN(lrelu(LN(xyz@W0+b0))@W1+b1))  per point
// ---------------------------------------------------------------------------
__global__ void __launch_bounds__(256) kA(
    const float* __restrict__ pc,
    const float* __restrict__ W0, const float* __restrict__ b0,
    const float* __restrict__ g0, const float* __restrict__ be0,
    const float* __restrict__ W1, const float* __restrict__ b1,
    const float* __restrict__ g1, const float* __restrict__ be1)
{
    int i = blockIdx.x*256 + threadIdx.x;
    int b = i >> 10, n = i & 1023;
    const float* p = pc + (size_t)b*3072;
    float x = p[n], y = p[1024+n], z = p[2048+n];

    float t[16];
    #pragma unroll
    for (int c=0;c<16;c++)
        t[c] = fmaf(x, __ldg(&W0[c]), fmaf(y, __ldg(&W0[16+c]), fmaf(z, __ldg(&W0[32+c]), __ldg(&b0[c]))));
    {
        float m=0.f;
        #pragma unroll
        for (int c=0;c<16;c++) m += t[c];
        m *= (1.f/16.f);
        float v=0.f;
        #pragma unroll
        for (int c=0;c<16;c++){ float dd=t[c]-m; v = fmaf(dd,dd,v); }
        v *= (1.f/16.f);
        float inv = rsqrtf(v + 1e-5f);
        #pragma unroll
        for (int c=0;c<16;c++)
            t[c] = lrelu(fmaf((t[c]-m)*inv, __ldg(&g0[c]), __ldg(&be0[c])));
    }
    float u[16];
    #pragma unroll
    for (int o=0;o<16;o++){
        float a = __ldg(&b1[o]);
        #pragma unroll
        for (int c=0;c<16;c++) a = fmaf(t[c], __ldg(&W1[c*16+o]), a);
        u[o] = a;
    }
    {
        float m=0.f;
        #pragma unroll
        for (int c=0;c<16;c++) m += u[c];
        m *= (1.f/16.f);
        float v=0.f;
        #pragma unroll
        for (int c=0;c<16;c++){ float dd=u[c]-m; v = fmaf(dd,dd,v); }
        v *= (1.f/16.f);
        float inv = rsqrtf(v + 1e-5f);
        #pragma unroll
        for (int c=0;c<16;c++)
            u[c] = lrelu(fmaf((u[c]-m)*inv, __ldg(&g1[c]), __ldg(&be1[c])));
    }
    float4* o4 = reinterpret_cast<float4*>(g_feat + (size_t)i*16);
    o4[0] = make_float4(u[0],u[1],u[2],u[3]);
    o4[1] = make_float4(u[4],u[5],u[6],u[7]);
    o4[2] = make_float4(u[8],u[9],u[10],u[11]);
    o4[3] = make_float4(u[12],u[13],u[14],u[15]);
}

// ---------------------------------------------------------------------------
// Kernel B: pointconv1 (K=16 NN of 512 queries over 1024 pts) + fused squeeze
// grid (4, B): 128 queries per block, one warp per query.
// ---------------------------------------------------------------------------
__global__ void __launch_bounds__(256, 3) kB(
    const float* __restrict__ pc,
    const float* __restrict__ Wp, const float* __restrict__ bp,
    const float* __restrict__ Ws, const float* __restrict__ bsv)
{
    __shared__ __align__(16) float4 sp4[1024];
    __shared__ __align__(16) float  sg[8][16][20];
    __shared__ float  scand[8][32];
    __shared__ int    sidxs[8][32];
    __shared__ __align__(16) float  smx[8][32];

    int b    = blockIdx.y;
    int base = blockIdx.x * 128;
    int tid  = threadIdx.x;
    int lane = tid & 31;
    int w    = tid >> 5;

    const float* p = pc + (size_t)b*3072;
    for (int n = tid; n < 1024; n += 256){
        float X = p[n], Y = p[1024+n], Z = p[2048+n];
        sp4[n] = make_float4(X, Y, Z, fmaf(X,X, fmaf(Y,Y, Z*Z)));
    }
    __syncthreads();

    // packed per-lane GEMM weights: lane = output channel
    unsigned long long wp[9];
    #pragma unroll
    for (int c=0;c<9;c++)
        wp[c] = pk(__ldg(&Wp[(2*c)*32 + lane]), __ldg(&Wp[(2*c+1)*32 + lane]));
    float wr18 = __ldg(&Wp[18*32 + lane]);
    unsigned long long accp = pk(__ldg(&bp[lane]), 0.f);

    // squeeze weights: lane handles output j = lane&7 over c in [cb, cb+8)
    int jq = lane & 7, cb = (lane >> 3) * 8;
    unsigned long long wsp[4];
    #pragma unroll
    for (int i=0;i<4;i++)
        wsp[i] = pk(__ldg(&Ws[(cb+2*i)*8 + jq]), __ldg(&Ws[(cb+2*i+1)*8 + jq]));
    float bsq = __ldg(&bsv[jq]);

    for (int m = base + w; m < base + 128; m += 8){
        int qi = 2*m;                                   // xyz1[m] == xyz0[2m]
        float4 q = sp4[qi];

        int kidx = knn16_select<32>(sp4, q.x, q.y, q.z, lane,
                                    &scand[w][0], &sidxs[w][0]);

        // --- gather neighbors into per-warp smem g[16][19] ------------------
        __syncwarp();
        if (lane < 16){
            int j = kidx;
            float4 xj = sp4[j];
            float* gr = &sg[w][lane][0];
            gr[0]=xj.x-q.x; gr[1]=xj.y-q.y; gr[2]=xj.z-q.z;
            const float4* fr = reinterpret_cast<const float4*>(g_feat + ((size_t)b*1024 + j)*16);
            float4 f0=fr[0], f1=fr[1], f2v=fr[2], f3=fr[3];
            gr[3]=f0.x;  gr[4]=f0.y;  gr[5]=f0.z;  gr[6]=f0.w;
            gr[7]=f1.x;  gr[8]=f1.y;  gr[9]=f1.z;  gr[10]=f1.w;
            gr[11]=f2v.x; gr[12]=f2v.y; gr[13]=f2v.z; gr[14]=f2v.w;
            gr[15]=f3.x; gr[16]=f3.y; gr[17]=f3.z; gr[18]=f3.w;
        }
        __syncwarp();

        // --- GEMM (lane = output channel) via packed FFMA2 + maxpool -------
        float mx = -BIGF;
        #pragma unroll 4
        for (int k=0;k<16;k++){
            const float* gr = &sg[w][k][0];
            ulonglong2 pA = *reinterpret_cast<const ulonglong2*>(gr);
            ulonglong2 pB = *reinterpret_cast<const ulonglong2*>(gr+4);
            ulonglong2 pC = *reinterpret_cast<const ulonglong2*>(gr+8);
            ulonglong2 pD = *reinterpret_cast<const ulonglong2*>(gr+12);
            float2 tl = *reinterpret_cast<const float2*>(gr+16);
            float  g18 = gr[18];
            unsigned long long acc = accp;
            acc = ffma2(pA.x, wp[0], acc);
            acc = ffma2(pA.y, wp[1], acc);
            acc = ffma2(pB.x, wp[2], acc);
            acc = ffma2(pB.y, wp[3], acc);
            acc = ffma2(pC.x, wp[4], acc);
            acc = ffma2(pC.y, wp[5], acc);
            acc = ffma2(pD.x, wp[6], acc);
            acc = ffma2(pD.y, wp[7], acc);
            acc = ffma2(pk(tl.x, tl.y), wp[8], acc);
            float2 s = upk(acc);
            float a = fmaf(g18, wr18, s.x + s.y);
            mx = fmaxf(mx, lrelu(a));
        }

        // --- fused squeeze via smem transpose: fs = lrelu(mx @ Ws + bs) -----
        smx[w][lane] = mx;
        __syncwarp();
        const unsigned long long* mp =
            reinterpret_cast<const unsigned long long*>(&smx[w][cb]);
        unsigned long long s2 = pk(0.f, 0.f);
        s2 = ffma2(mp[0], wsp[0], s2);
        s2 = ffma2(mp[1], wsp[1], s2);
        s2 = ffma2(mp[2], wsp[2], s2);
        s2 = ffma2(mp[3], wsp[3], s2);
        float2 sv = upk(s2);
        float s = sv.x + sv.y;
        s += __shfl_down_sync(FULLM, s, 16);
        s += __shfl_down_sync(FULLM, s, 8);
        if (lane < 8)
            g_fs[((size_t)b*512 + m)*8 + jq] = lrelu(s + bsq);
    }
}

// ---------------------------------------------------------------------------
// Kernel C: pointconv2 (128 queries, 512 candidates, 11ch -> 128ch),
// fused column-sum (mean commutes with the final linear map).
// grid (2, B): 64 queries per block, one warp per query.
// ---------------------------------------------------------------------------
__global__ void __launch_bounds__(256) kC(
    const float* __restrict__ pc,
    const float* __restrict__ Wc, const float* __restrict__ bc)
{
    __shared__ __align__(16) float4 sp4[512];
    __shared__ __align__(16) float  sf[512*8];
    __shared__ __align__(16) float  sg[8][16][12];
    __shared__ float  scand[8][32];
    __shared__ int    sidxs[8][32];
    __shared__ float  sacc[8][128];

    int b    = blockIdx.y;
    int base = blockIdx.x * 64;
    int tid  = threadIdx.x;
    int lane = tid & 31;
    int w    = tid >> 5;

    const float* p = pc + (size_t)b*3072;
    for (int m = tid; m < 512; m += 256){
        float X = p[2*m], Y = p[1024+2*m], Z = p[2048+2*m]; // xyz1[m]=xyz0[2m]
        sp4[m] = make_float4(X, Y, Z, fmaf(X,X, fmaf(Y,Y, Z*Z)));
    }
    {
        const float4* src = reinterpret_cast<const float4*>(g_fs + (size_t)b*4096);
        float4* dst = reinterpret_cast<float4*>(sf);
        for (int t = tid; t < 1024; t += 256) dst[t] = src[t];
    }
    __syncthreads();

    // packed weights for 4 output channels per lane (lane, lane+32, +64, +96)
    unsigned long long wq0[5], wq1[5], wq2[5], wq3[5];
    #pragma unroll
    for (int c=0;c<5;c++){
        wq0[c] = pk(__ldg(&Wc[(2*c)*128 + lane]),      __ldg(&Wc[(2*c+1)*128 + lane]));
        wq1[c] = pk(__ldg(&Wc[(2*c)*128 + lane + 32]), __ldg(&Wc[(2*c+1)*128 + lane + 32]));
        wq2[c] = pk(__ldg(&Wc[(2*c)*128 + lane + 64]), __ldg(&Wc[(2*c+1)*128 + lane + 64]));
        wq3[c] = pk(__ldg(&Wc[(2*c)*128 + lane + 96]), __ldg(&Wc[(2*c+1)*128 + lane + 96]));
    }
    float w10_0 = __ldg(&Wc[10*128 + lane]),      w10_1 = __ldg(&Wc[10*128 + lane + 32]);
    float w10_2 = __ldg(&Wc[10*128 + lane + 64]), w10_3 = __ldg(&Wc[10*128 + lane + 96]);
    unsigned long long bp0 = pk(__ldg(&bc[lane]),     0.f);
    unsigned long long bp1 = pk(__ldg(&bc[lane+32]),  0.f);
    unsigned long long bp2 = pk(__ldg(&bc[lane+64]),  0.f);
    unsigned long long bp3 = pk(__ldg(&bc[lane+96]),  0.f);

    float acc0 = 0.f, acc1 = 0.f, acc2 = 0.f, acc3 = 0.f;

    for (int m2 = base + w; m2 < base + 64; m2 += 8){
        int qi = 4*m2;                                  // xyz2[m2] == xyz1[4*m2]
        float4 q = sp4[qi];

        int kidx = knn16_select<16>(sp4, q.x, q.y, q.z, lane,
                                    &scand[w][0], &sidxs[w][0]);

        __syncwarp();
        if (lane < 16){
            int j = kidx;
            float4 xj = sp4[j];
            float* gr = &sg[w][lane][0];
            gr[0]=xj.x-q.x; gr[1]=xj.y-q.y; gr[2]=xj.z-q.z;
            const float4* fr = reinterpret_cast<const float4*>(sf + j*8);
            float4 f0=fr[0], f1=fr[1];
            gr[3]=f0.x; gr[4]=f0.y; gr[5]=f0.z; gr[6]=f0.w;
            gr[7]=f1.x; gr[8]=f1.y; gr[9]=f1.z; gr[10]=f1.w;
        }
        __syncwarp();

        float mx0=-BIGF, mx1=-BIGF, mx2=-BIGF, mx3=-BIGF;
        #pragma unroll 4
        for (int k=0;k<16;k++){
            const float* gr = &sg[w][k][0];
            ulonglong2 pA = *reinterpret_cast<const ulonglong2*>(gr);     // g0..g3
            ulonglong2 pB = *reinterpret_cast<const ulonglong2*>(gr+4);   // g4..g7
            float4     v2 = *reinterpret_cast<const float4*>(gr+8);       // g8..g11(pad)
            unsigned long long p4 = pk(v2.x, v2.y);
            float g10 = v2.z;
            unsigned long long a0=bp0, a1=bp1, a2=bp2, a3=bp3;
            a0 = ffma2(pA.x, wq0[0], a0); a1 = ffma2(pA.x, wq1[0], a1);
            a2 = ffma2(pA.x, wq2[0], a2); a3 = ffma2(pA.x, wq3[0], a3);
            a0 = ffma2(pA.y, wq0[1], a0); a1 = ffma2(pA.y, wq1[1], a1);
            a2 = ffma2(pA.y, wq2[1], a2); a3 = ffma2(pA.y, wq3[1], a3);
            a0 = ffma2(pB.x, wq0[2], a0); a1 = ffma2(pB.x, wq1[2], a1);
            a2 = ffma2(pB.x, wq2[2], a2); a3 = ffma2(pB.x, wq3[2], a3);
            a0 = ffma2(pB.y, wq0[3], a0); a1 = ffma2(pB.y, wq1[3], a1);
            a2 = ffma2(pB.y, wq2[3], a2); a3 = ffma2(pB.y, wq3[3], a3);
            a0 = ffma2(p4,   wq0[4], a0); a1 = ffma2(p4,   wq1[4], a1);
            a2 = ffma2(p4,   wq2[4], a2); a3 = ffma2(p4,   wq3[4], a3);
            float2 s0 = upk(a0), s1 = upk(a1), s2 = upk(a2), s3 = upk(a3);
            float r0 = fmaf(g10, w10_0, s0.x + s0.y);
            float r1 = fmaf(g10, w10_1, s1.x + s1.y);
            float r2 = fmaf(g10, w10_2, s2.x + s2.y);
            float r3 = fmaf(g10, w10_3, s3.x + s3.y);
            mx0 = fmaxf(mx0, lrelu(r0));
            mx1 = fmaxf(mx1, lrelu(r1));
            mx2 = fmaxf(mx2, lrelu(r2));
            mx3 = fmaxf(mx3, lrelu(r3));
        }
        acc0 += mx0; acc1 += mx1; acc2 += mx2; acc3 += mx3;
    }

    // deterministic in-block reduction of per-warp partial sums
    sacc[w][lane]    = acc0;
    sacc[w][lane+32] = acc1;
    sacc[w][lane+64] = acc2;
    sacc[w][lane+96] = acc3;
    __syncthreads();
    if (tid < 128){
        float s = sacc[0][tid];
        #pragma unroll
        for (int ww=1; ww<8; ww++) s += sacc[ww][tid];
        g_psum[((size_t)b*2 + blockIdx.x)*128 + tid] = s;
    }
}

// ---------------------------------------------------------------------------
// Kernel D: out[b] = (psum0+psum1)/128 @ We + be
// ---------------------------------------------------------------------------
__global__ void __launch_bounds__(256) kD(
    const float* __restrict__ We, const float* __restrict__ be,
    float* __restrict__ out)
{
    __shared__ float sbar[128];
    int b = blockIdx.x, tid = threadIdx.x;
    if (tid < 128){
        float s = g_psum[((size_t)b*2)*128 + tid] + g_psum[((size_t)b*2+1)*128 + tid];
        sbar[tid] = s * (1.f/128.f);
    }
    __syncthreads();
    float acc = __ldg(&be[tid]);
    #pragma unroll 8
    for (int c=0;c<128;c++) acc = fmaf(sbar[c], __ldg(&We[c*256 + tid]), acc);
    out[(size_t)b*256 + tid] = acc;
}

// ---------------------------------------------------------------------------
extern "C" void kernel_launch(void* const* d_in, const int* in_sizes, int n_in,
                              void* d_out, int out_size)
{
    (void)in_sizes; (void)n_in; (void)out_size;
    const float* pc  = (const float*)d_in[0];
    const float* W0  = (const float*)d_in[1];
    const float* b0  = (const float*)d_in[2];
    const float* g0  = (const float*)d_in[3];
    const float* be0 = (const float*)d_in[4];
    const float* W1  = (const float*)d_in[5];
    const float* b1  = (const float*)d_in[6];
    const float* g1  = (const float*)d_in[7];
    const float* be1 = (const float*)d_in[8];
    const float* Wp  = (const float*)d_in[9];
    const float* bp  = (const float*)d_in[10];
    const float* Ws  = (const float*)d_in[11];
    const float* bsv = (const float*)d_in[12];
    const float* Wc  = (const float*)d_in[13];
    const float* bc  = (const float*)d_in[14];
    const float* We  = (const float*)d_in[15];
    const float* be  = (const float*)d_in[16];
    float* out = (float*)d_out;

    kA<<<1024, 256>>>(pc, W0, b0, g0, be0, W1, b1, g1, be1);
    dim3 gB(4, 256);
    kB<<<gB, 256>>>(pc, Wp, bp, Ws, bsv);
    dim3 gC(2, 256);
    kC<<<gC, 256>>>(pc, Wc, bc);
    kD<<<256, 256>>>(We, be, out);
}